// round 1
// baseline (speedup 1.0000x reference)
#include <cuda_runtime.h>
#include <math.h>

#define NB 128
#define NL 512
#define NH 336
#define ND 256
#define NTXT 768
#define NK 16
#define NEMB 128
#define HSCALE 0.15f
#define EPSV 0.05f
#define NITERS 30
#define ALPHAV 1.0f
#define BETAV 0.5f
#define GWV 0.5f
#define TAUV 0.07f
#define SHIFT 56   // max(1, H//6)

// ---------------- device scratch (allocation-free rule: __device__ globals) ----------
__device__ __align__(16) float g_ytir[NB*NH];
__device__ __align__(16) float g_r[NB*NK];
__device__ __align__(16) float g_mu[NB*NK];
__device__ __align__(16) float g_kn[NB*NK*NEMB];
__device__ __align__(16) float g_tsg[NB*ND];
__device__ __align__(16) float g_gate[NB*ND];
__device__ __align__(16) float g_Wcat[256*384];
__device__ __align__(16) float g_T[(size_t)NB*NH*384];
__device__ __align__(16) float g_fpos[(size_t)NB*NH*NEMB];
__device__ __align__(16) float g_invn[NB*NH];
__device__ double g_acc[8];   // 0:mse 1:cot 2:delta 3:ent(sum sw*log sw) 4:tv

__device__ __forceinline__ float softplusf(float x){
    return fmaxf(x,0.f) + log1pf(expf(-fabsf(x)));
}
__device__ __forceinline__ float sigmoidf(float x){
    return 1.f/(1.f+expf(-x));
}

// ---------------- zero partials ----------------
__global__ void kZ0(){
    if (threadIdx.x < 8) g_acc[threadIdx.x] = 0.0;
}

// ---------------- Wcat prep: fold diff operators into one [256 x 384] matrix --------
// f_pos[h] = y[h]@A - y[h-1]@Bm + y[h-2]@W3,  A=W1+W2+W3, Bm=W2+2W3 (clamped idx at h<2)
__global__ void kWcat(const float* __restrict__ Wfp){
    int idx = blockIdx.x*blockDim.x + threadIdx.x;
    if (idx >= 256*384) return;
    int c = idx/384, j = idx%384;
    float v;
    if (j < 128){ int e=j;     v = Wfp[c*128+e] + Wfp[(256+c)*128+e] + Wfp[(512+c)*128+e]; }
    else if (j < 256){ int e=j-128; v = Wfp[(256+c)*128+e] + 2.f*Wfp[(512+c)*128+e]; }
    else { int e=j-256; v = Wfp[(512+c)*128+e]; }
    g_Wcat[idx] = v;
}

// ---------------- kA: text->kernels, kappa, y_tir_scalar, r, mu, kn, ent, tv --------
__global__ void kA(const float* __restrict__ text, const float* __restrict__ Wt2k,
                   const float* __restrict__ bt2k, const float* __restrict__ Wkemb,
                   const float* __restrict__ bkemb){
    int b = blockIdx.x, tid = threadIdx.x;   // 128 threads
    __shared__ float tx[NTXT];
    __shared__ float raw[112];
    __shared__ float kap[NK][NH];
    __shared__ float mus[NK], sigs[NK], amps[NK], sws[NK][4];
    __shared__ float kemb[NK][NEMB];
    __shared__ float red[NK], ent_s[NK];
    __shared__ float rtot;

    for (int i=tid;i<NTXT;i+=128) tx[i]=text[b*NTXT+i];
    __syncthreads();
    if (tid < 112){
        float acc = bt2k[tid];
        for (int i=0;i<NTXT;i++) acc += tx[i]*Wt2k[i*112+tid];
        raw[tid]=acc;
    }
    __syncthreads();
    if (tid < NK){
        int k=tid;
        float mu  = sigmoidf(raw[k*7+0]);
        float sig = softplusf(raw[k*7+1])*HSCALE + 1e-3f;
        float amp = softplusf(raw[k*7+2]);
        float s3=raw[k*7+3], s4=raw[k*7+4], s5=raw[k*7+5], s6=raw[k*7+6];
        float mx=fmaxf(fmaxf(s3,s4),fmaxf(s5,s6));
        float e3=expf(s3-mx),e4=expf(s4-mx),e5=expf(s5-mx),e6=expf(s6-mx);
        float es=e3+e4+e5+e6;
        sws[k][0]=e3/es; sws[k][1]=e4/es; sws[k][2]=e5/es; sws[k][3]=e6/es;
        mus[k]=mu; sigs[k]=sig; amps[k]=amp;
        g_mu[b*NK+k]=mu;
        float ent=0.f;
        #pragma unroll
        for (int s=0;s<4;s++){ float sc=fmaxf(sws[k][s],1e-8f); ent += sc*logf(sc); }
        ent_s[k]=ent;
    }
    __syncthreads();
    for (int k=0;k<NK;k++){
        float mu=mus[k], sig=sigs[k], amp=amps[k];
        float w0=sws[k][0],w1=sws[k][1],w2=sws[k][2],w3=sws[k][3];
        for (int h=tid;h<NH;h+=128){
            float t=(h+0.5f)/(float)NH;
            float z=(t-mu)/sig;
            float az=fabsf(z);
            float b0=expf(-0.5f*z*z);
            float b1=expf(-az);
            float b2=fmaxf(1.f-az,0.f);
            float zc=fminf(fmaxf(z,-1.f),1.f);
            float b3=(az<=1.f)?0.5f*(1.f+cosf(3.14159265358979f*zc)):0.f;
            kap[k][h]=amp*(w0*b0+w1*b1+w2*b2+w3*b3);
        }
    }
    __syncthreads();
    for (int h=tid;h<NH;h+=128){
        float s=0.f;
        #pragma unroll
        for (int k=0;k<NK;k++) s+=kap[k][h];
        g_ytir[b*NH+h]=s;
    }
    if (tid<NK){
        float s=0.f;
        for (int h=0;h<NH;h++) s+=kap[tid][h];
        red[tid]=s+1e-6f;
    }
    __syncthreads();
    if (tid==0){
        float t=0.f; for (int kk=0;kk<NK;kk++) t+=red[kk];
        rtot=t;
        float ent=0.f; for (int kk=0;kk<NK;kk++) ent+=ent_s[kk];
        float tv=0.f;  for (int kk=1;kk<NK;kk++) tv+=fabsf(mus[kk]-mus[kk-1]);
        atomicAdd(&g_acc[3], (double)ent);
        atomicAdd(&g_acc[4], (double)tv);
    }
    __syncthreads();
    if (tid<NK) g_r[b*NK+tid]=red[tid]/rtot;
    // k_emb = kappa @ W_kemb + b, then l2-normalize
    int e = tid;  // exactly NEMB threads
    for (int k=0;k<NK;k++){
        float acc=bkemb[e];
        for (int h=0;h<NH;h++) acc += kap[k][h]*Wkemb[h*NEMB+e];
        kemb[k][e]=acc;
    }
    __syncthreads();
    if (tid<NK){
        float s=0.f;
        for (int i=0;i<NEMB;i++){ float v=kemb[tid][i]; s+=v*v; }
        red[tid]=1.f/(sqrtf(s)+1e-8f);
    }
    __syncthreads();
    for (int k=0;k<NK;k++) g_kn[(b*NK+k)*NEMB+e]=kemb[k][e]*red[k];
}

// ---------------- kB: ts_global = mean over L ----------------
__global__ void kB(const float* __restrict__ enc){
    int b=blockIdx.x, d=threadIdx.x;  // 256 threads
    const float* p = enc + (size_t)b*NL*ND + d;
    float s=0.f;
    #pragma unroll 8
    for (int l=0;l<NL;l++) s += p[(size_t)l*ND];
    g_tsg[b*ND+d]=s*(1.f/(float)NL);
}

// ---------------- kC: gate MLP (4 batches per block) ----------------
__global__ void kC(const float* __restrict__ text, const float* __restrict__ varp,
                   const float* __restrict__ Wg1, const float* __restrict__ bg1,
                   const float* __restrict__ Wg2, const float* __restrict__ bg2){
    int b0=blockIdx.x*4, tid=threadIdx.x;  // 256 threads
    __shared__ float xin[4][1280];
    __shared__ float hid[4][512];
    for (int bb=0;bb<4;bb++){
        int b=b0+bb;
        for (int i=tid;i<ND;i+=256)   xin[bb][i]=g_tsg[b*ND+i];
        for (int i=tid;i<NTXT;i+=256) xin[bb][ND+i]=text[b*NTXT+i];
        for (int i=tid;i<ND;i+=256)   xin[bb][ND+NTXT+i]=varp[i];
    }
    __syncthreads();
    for (int j=tid;j<512;j+=256){
        float a0=bg1[j],a1=a0,a2=a0,a3=a0;
        for (int i=0;i<1280;i++){
            float w=Wg1[i*512+j];
            a0+=xin[0][i]*w; a1+=xin[1][i]*w; a2+=xin[2][i]*w; a3+=xin[3][i]*w;
        }
        hid[0][j]=fmaxf(a0,0.f); hid[1][j]=fmaxf(a1,0.f);
        hid[2][j]=fmaxf(a2,0.f); hid[3][j]=fmaxf(a3,0.f);
    }
    __syncthreads();
    int d=tid;
    float a0=bg2[d],a1=a0,a2=a0,a3=a0;
    for (int j=0;j<512;j++){
        float w=Wg2[j*256+d];
        a0+=hid[0][j]*w; a1+=hid[1][j]*w; a2+=hid[2][j]*w; a3+=hid[3][j]*w;
    }
    g_gate[(b0+0)*ND+d]=sigmoidf(a0);
    g_gate[(b0+1)*ND+d]=sigmoidf(a1);
    g_gate[(b0+2)*ND+d]=sigmoidf(a2);
    g_gate[(b0+3)*ND+d]=sigmoidf(a3);
}

// ---------------- kD: mse loss ----------------
__global__ void kD(const float* __restrict__ yres, const float* __restrict__ yfut,
                   const float* __restrict__ Wtir, const float* __restrict__ btir,
                   const float* __restrict__ varp){
    const float4* yr4=(const float4*)yres; const float4* yf4=(const float4*)yfut;
    const float4* g4 =(const float4*)g_gate;
    const float4* wt4=(const float4*)Wtir; const float4* bt4=(const float4*)btir;
    const float4* vp4=(const float4*)varp;
    float acc=0.f;
    const int total=NB*NH*ND/4;
    for (int i=blockIdx.x*blockDim.x+threadIdx.x; i<total; i+=gridDim.x*blockDim.x){
        int d4 = i % (ND/4);
        int bh = i / (ND/4);
        int h = bh % NH, b = bh / NH;
        float s = g_ytir[b*NH+h];
        float4 yr=yr4[i], yf=yf4[i];
        float4 wt=wt4[d4], bt=bt4[d4], vp=vp4[d4];
        float4 gg=g4[b*(ND/4)+d4];
        float t0=(s*wt.x+bt.x)*vp.x, t1=(s*wt.y+bt.y)*vp.y;
        float t2=(s*wt.z+bt.z)*vp.z, t3=(s*wt.w+bt.w)*vp.w;
        float h0=yr.x+GWV*gg.x*(t0-yr.x), h1=yr.y+GWV*gg.y*(t1-yr.y);
        float h2=yr.z+GWV*gg.z*(t2-yr.z), h3=yr.w+GWV*gg.w*(t3-yr.w);
        float d0=h0-yf.x, d1=h1-yf.y, d2=h2-yf.z, d3=h3-yf.w;
        acc += d0*d0 + d1*d1 + d2*d2 + d3*d3;
    }
    __shared__ float sred[256];
    sred[threadIdx.x]=acc; __syncthreads();
    for (int s=128;s>0;s>>=1){
        if (threadIdx.x<s) sred[threadIdx.x]+=sred[threadIdx.x+s];
        __syncthreads();
    }
    if (threadIdx.x==0) atomicAdd(&g_acc[0],(double)sred[0]);
}

// ---------------- kGEMM: T = y_future[43008x256] @ Wcat[256x384] ----------------
__global__ void __launch_bounds__(256) kGEMM(const float* __restrict__ Y){
    __shared__ float As[16][128];
    __shared__ float Bs[16][128];
    int m0=blockIdx.x*128, n0=blockIdx.y*128;
    int tid=threadIdx.x;
    int tx=tid%16, ty=tid/16;
    float acc[8][8];
    #pragma unroll
    for (int i=0;i<8;i++)
        #pragma unroll
        for (int j=0;j<8;j++) acc[i][j]=0.f;

    for (int k0=0;k0<256;k0+=16){
        #pragma unroll
        for (int r=0;r<2;r++){
            int idx=tid+r*256;
            int m=idx>>2, kq=idx&3;
            float4 v=*(const float4*)(Y + (size_t)(m0+m)*256 + k0 + kq*4);
            As[kq*4+0][m]=v.x; As[kq*4+1][m]=v.y; As[kq*4+2][m]=v.z; As[kq*4+3][m]=v.w;
        }
        #pragma unroll
        for (int r=0;r<2;r++){
            int idx=tid+r*256;
            int k=idx>>5, nq=idx&31;
            float4 v=*(const float4*)(g_Wcat + (k0+k)*384 + n0 + nq*4);
            *(float4*)&Bs[k][nq*4]=v;
        }
        __syncthreads();
        #pragma unroll
        for (int kk=0;kk<16;kk++){
            float a[8], bb[8];
            *(float4*)&a[0]=*(float4*)&As[kk][ty*8];
            *(float4*)&a[4]=*(float4*)&As[kk][ty*8+4];
            *(float4*)&bb[0]=*(float4*)&Bs[kk][tx*8];
            *(float4*)&bb[4]=*(float4*)&Bs[kk][tx*8+4];
            #pragma unroll
            for (int i=0;i<8;i++)
                #pragma unroll
                for (int j=0;j<8;j++)
                    acc[i][j] += a[i]*bb[j];
        }
        __syncthreads();
    }
    #pragma unroll
    for (int i=0;i<8;i++){
        float* dst = g_T + (size_t)(m0+ty*8+i)*384 + n0 + tx*8;
        *(float4*)dst     = make_float4(acc[i][0],acc[i][1],acc[i][2],acc[i][3]);
        *(float4*)(dst+4) = make_float4(acc[i][4],acc[i][5],acc[i][6],acc[i][7]);
    }
}

// ---------------- kF: shift-combine epilogue + row norms ----------------
__global__ void kF(const float* __restrict__ bfp){
    int m=blockIdx.x; int e=threadIdx.x;   // 128 threads
    int b=m/NH, h=m%NH;
    int m1=b*NH + (h>0?h-1:0);
    int m2=b*NH + (h>1?h-2:0);
    float v = g_T[(size_t)m*384+e] - g_T[(size_t)m1*384+128+e] + g_T[(size_t)m2*384+256+e] + bfp[e];
    g_fpos[(size_t)m*NEMB+e]=v;
    float sq=v*v;
    #pragma unroll
    for (int o=16;o>0;o>>=1) sq+=__shfl_down_sync(0xffffffffu,sq,o);
    __shared__ float w[4];
    if ((threadIdx.x&31)==0) w[threadIdx.x>>5]=sq;
    __syncthreads();
    if (threadIdx.x==0){
        float s=w[0]+w[1]+w[2]+w[3];
        g_invn[m]=1.f/(sqrtf(s)+1e-8f);
    }
}

// ---------------- kG: per-batch mega kernel: C, Sinkhorn, Pi, cot, contrastive -----
__global__ void __launch_bounds__(512) kG(const int* __restrict__ perm){
    int b=blockIdx.x, tid=threadIdx.x;
    extern __shared__ float sm[];
    float* kn   = sm;              // 2048
    float* Csh  = kn+2048;         // 5376
    float* Km   = Csh+5376;        // 5376
    float* ft   = Km+5376;         // 32*129 = 4128
    float* aggp = ft+4128;         // 2048
    float* aggn = aggp+2048;       // 2048
    float* u    = aggn+2048;       // 16
    float* v    = u+16;            // 336
    float* rr   = v+336;           // 16
    float* mus  = rr+16;           // 16
    float* scr  = mus+16;          // 64
    int* permi  = (int*)(scr+64);  // 128

    for (int i=tid;i<NK*NEMB;i+=512) kn[i]=g_kn[b*NK*NEMB+i];
    if (tid<NK){ rr[tid]=g_r[b*NK+tid]; mus[tid]=g_mu[b*NK+tid]; }
    if (tid<NEMB) permi[tid]=perm[tid];
    if (tid<NH) v[tid]=1.f;
    __syncthreads();

    int k    = tid>>5, lane = tid&31;   // warp id 0..15
    int kq   = tid>>7, e    = tid&127;  // aggregation mapping
    int ck   = tid>>5, chh  = tid&31;   // C mapping

    // ---- cost matrix C + Kmat ----
    for (int h0=0;h0<NH;h0+=32){
        int hv=min(32,NH-h0);
        for (int i=tid;i<32*128;i+=512){
            int r2=i>>7, c=i&127;
            if (r2<hv) ft[r2*129+c]=g_fpos[((size_t)(b*NH+h0+r2))*NEMB+c];
        }
        __syncthreads();
        if (chh<hv){
            int h=h0+chh;
            float s=0.f;
            const float* knk=&kn[ck*128];
            const float* fr=&ft[chh*129];
            #pragma unroll 8
            for (int ee=0;ee<128;ee++) s+=knk[ee]*fr[ee];
            float cosv = s*g_invn[b*NH+h];
            float t=(h+0.5f)/(float)NH;
            float C = ALPHAV*(1.f-cosv) + BETAV*fmaxf(mus[ck]-t,0.f);
            Csh[ck*NH+h]=C;
            Km[ck*NH+h]=expf(-C*(1.f/EPSV));
        }
        __syncthreads();
    }

    // ---- Sinkhorn (30 iterations) ----
    for (int it=0; it<NITERS; it++){
        {
            float s=0.f;
            for (int h=lane;h<NH;h+=32) s+=Km[k*NH+h]*v[h];
            #pragma unroll
            for (int o=16;o>0;o>>=1) s+=__shfl_down_sync(0xffffffffu,s,o);
            if (lane==0) u[k]=rr[k]/(s+1e-9f);
        }
        __syncthreads();
        if (tid<NH){
            float s=0.f;
            #pragma unroll
            for (int kk=0;kk<NK;kk++) s+=Km[kk*NH+tid]*u[kk];
            v[tid]=(1.f/(float)NH)/(s+1e-9f);
        }
        __syncthreads();
    }

    // ---- Pi (overwrite Km) + cot partial ----
    float cot=0.f;
    for (int i=tid;i<NK*NH;i+=512){
        int kk=i/NH, h=i%NH;
        float pi=u[kk]*Km[i]*v[h];
        Km[i]=pi;
        cot+=Csh[i]*pi;
    }
    #pragma unroll
    for (int o=16;o>0;o>>=1) cot+=__shfl_down_sync(0xffffffffu,cot,o);
    if (lane==0) scr[k]=cot;
    __syncthreads();
    if (tid==0){
        float s=0.f; for (int i=0;i<16;i++) s+=scr[i];
        atomicAdd(&g_acc[1],(double)s);
    }
    // ---- w = Pi / rowsum ----
    {
        float s=0.f;
        for (int h=lane;h<NH;h+=32) s+=Km[k*NH+h];
        #pragma unroll
        for (int o=16;o>0;o>>=1) s+=__shfl_down_sync(0xffffffffu,s,o);
        if (lane==0) scr[16+k]=1.f/(s+1e-9f);
    }
    __syncthreads();
    for (int i=tid;i<NK*NH;i+=512) Km[i]*=scr[16+i/NH];
    __syncthreads();

    // ---- transport-weighted aggregations (pos + rolled-w neg1) ----
    float accp[4]={0,0,0,0}, accn[4]={0,0,0,0};
    for (int h0=0;h0<NH;h0+=32){
        int hv=min(32,NH-h0);
        for (int i=tid;i<32*128;i+=512){
            int r2=i>>7, c=i&127;
            if (r2<hv) ft[r2*129+c]=g_fpos[((size_t)(b*NH+h0+r2))*NEMB+c];
        }
        __syncthreads();
        for (int hh=0;hh<hv;hh++){
            float f=ft[hh*129+e];
            int h=h0+hh;
            int hn=h+SHIFT; if (hn>=NH) hn-=NH;
            #pragma unroll
            for (int j=0;j<4;j++){
                int kk=kq*4+j;
                accp[j]+=Km[kk*NH+h ]*f;
                accn[j]+=Km[kk*NH+hn]*f;
            }
        }
        __syncthreads();
    }
    #pragma unroll
    for (int j=0;j<4;j++){
        aggp[(kq*4+j)*128+e]=accp[j];
        aggn[(kq*4+j)*128+e]=accn[j];
    }
    __syncthreads();

    // ---- sims + contrastive loss (neg2 via permuted aggp, same norm) ----
    {
        float sp=0,sn=0,dp=0,dn=0,d2=0;
        for (int ee=lane; ee<128; ee+=32){
            float ap=aggp[k*128+ee], an=aggn[k*128+ee], kv=kn[k*128+ee];
            sp+=ap*ap; sn+=an*an; dp+=kv*ap; dn+=kv*an;
            d2+=kv*aggp[k*128+permi[ee]];
        }
        #pragma unroll
        for (int o=16;o>0;o>>=1){
            sp+=__shfl_down_sync(0xffffffffu,sp,o);
            sn+=__shfl_down_sync(0xffffffffu,sn,o);
            dp+=__shfl_down_sync(0xffffffffu,dp,o);
            dn+=__shfl_down_sync(0xffffffffu,dn,o);
            d2+=__shfl_down_sync(0xffffffffu,d2,o);
        }
        if (lane==0){
            float ip=1.f/(sqrtf(sp)+1e-8f), in_=1.f/(sqrtf(sn)+1e-8f);
            float l0=dp*ip*(1.f/TAUV), l1=dn*in_*(1.f/TAUV), l2=d2*ip*(1.f/TAUV);
            float mx=fmaxf(l0,fmaxf(l1,l2));
            float lse=mx+logf(expf(l0-mx)+expf(l1-mx)+expf(l2-mx));
            scr[32+k]=lse-l0;
        }
    }
    __syncthreads();
    if (tid==0){
        float s=0.f; for (int i=0;i<16;i++) s+=scr[32+i];
        atomicAdd(&g_acc[2],(double)s);
    }
}

// ---------------- final combine ----------------
__global__ void kZF(float* out){
    double mse = g_acc[0]/((double)NB*NH*ND);
    double cot = g_acc[1]/(double)NB;
    double del = g_acc[2]/((double)NB*NK);
    double ent = -g_acc[3]/((double)NB*NK);
    double tv  = g_acc[4]/((double)NB*(NK-1));
    out[0]=(float)(1.0*mse + 0.1*cot + 0.1*del + 0.01*ent + 0.01*tv);
}

extern "C" void kernel_launch(void* const* d_in, const int* in_sizes, int n_in,
                              void* d_out, int out_size){
    const float* y_res =(const float*)d_in[0];
    const float* text  =(const float*)d_in[1];
    const float* enc   =(const float*)d_in[2];
    const float* yfut  =(const float*)d_in[3];
    const int*   perm  =(const int*)  d_in[4];
    const float* Wt2k  =(const float*)d_in[5];
    const float* bt2k  =(const float*)d_in[6];
    const float* Wkemb =(const float*)d_in[7];
    const float* bkemb =(const float*)d_in[8];
    const float* Wtir  =(const float*)d_in[9];
    const float* btir  =(const float*)d_in[10];
    const float* varp  =(const float*)d_in[11];
    const float* Wg1   =(const float*)d_in[12];
    const float* bg1   =(const float*)d_in[13];
    const float* Wg2   =(const float*)d_in[14];
    const float* bg2   =(const float*)d_in[15];
    const float* Wfp   =(const float*)d_in[16];
    const float* bfp   =(const float*)d_in[17];
    float* out=(float*)d_out;

    size_t smbytes = (size_t)(2048+5376+5376+4128+2048+2048+16+336+16+16+64+128)*4;
    cudaFuncSetAttribute(kG, cudaFuncAttributeMaxDynamicSharedMemorySize, (int)(96*1024));

    kZ0<<<1,32>>>();
    kWcat<<<(256*384+255)/256,256>>>(Wfp);
    kA<<<NB,128>>>(text,Wt2k,bt2k,Wkemb,bkemb);
    kB<<<NB,256>>>(enc);
    kC<<<NB/4,256>>>(text,varp,Wg1,bg1,Wg2,bg2);
    kD<<<2688,256>>>(y_res,yfut,Wtir,btir,varp);
    kGEMM<<<dim3(336,3),256>>>(yfut);
    kF<<<NB*NH,128>>>(bfp);
    kG<<<NB,512,smbytes>>>(perm);
    kZF<<<1,1>>>(out);
}

// round 5
// speedup vs baseline: 1.7632x; 1.7632x over previous
#include <cuda_runtime.h>
#include <stdint.h>
#include <math.h>

#define NB 128
#define NL 512
#define NH 336
#define ND 256
#define NTXT 768
#define NK 16
#define NEMB 128
#define HSCALE 0.15f
#define EPSV 0.05f
#define NITERS 30
#define ALPHAV 1.0f
#define BETAV 0.5f
#define GWV 0.5f
#define TAUV 0.07f
#define SHIFT 56   // max(1, H//6)

// ---------------- device scratch ----------------
__device__ __align__(16) float g_ytir[NB*NH];
__device__ __align__(16) float g_r[NB*NK];
__device__ __align__(16) float g_mu[NB*NK];
__device__ __align__(16) float g_kn[NB*NK*NEMB];
__device__ __align__(16) float g_tsg[NB*ND];
__device__ __align__(16) float g_gate[NB*ND];
__device__ __align__(16) float g_Wcat[256*384];
__device__ __align__(16) float g_T[(size_t)NB*NH*384];
__device__ __align__(16) float g_fpos[(size_t)NB*NH*NEMB];
__device__ __align__(16) float g_invn[NB*NH];
__device__ double g_acc[8];   // 0:mse 1:cot 2:delta 3:ent 4:tv

__device__ __forceinline__ float softplusf(float x){
    return fmaxf(x,0.f) + log1pf(expf(-fabsf(x)));
}
__device__ __forceinline__ float sigmoidf(float x){
    return 1.f/(1.f+expf(-x));
}

// ---------------- Wcat prep (+ zero accumulators) --------
__global__ void kWcat(const float* __restrict__ Wfp){
    if (blockIdx.x==0 && threadIdx.x<8) g_acc[threadIdx.x]=0.0;
    int idx = blockIdx.x*blockDim.x + threadIdx.x;
    if (idx >= 256*384) return;
    int c = idx/384, j = idx%384;
    float v;
    if (j < 128){ int e=j;     v = Wfp[c*128+e] + Wfp[(256+c)*128+e] + Wfp[(512+c)*128+e]; }
    else if (j < 256){ int e=j-128; v = Wfp[(256+c)*128+e] + 2.f*Wfp[(512+c)*128+e]; }
    else { int e=j-256; v = Wfp[(512+c)*128+e]; }
    g_Wcat[idx] = v;
}

// ---------------- kA: text->kernels etc --------
__global__ void kA(const float* __restrict__ text, const float* __restrict__ Wt2k,
                   const float* __restrict__ bt2k, const float* __restrict__ Wkemb,
                   const float* __restrict__ bkemb){
    int b = blockIdx.x, tid = threadIdx.x;   // 128 threads
    __shared__ float tx[NTXT];
    __shared__ float raw[112];
    __shared__ float kap[NK][NH];
    __shared__ float mus[NK], sigs[NK], amps[NK], sws[NK][4];
    __shared__ float red[NK], ent_s[NK];
    __shared__ float rtot;

    for (int i=tid;i<NTXT;i+=128) tx[i]=text[b*NTXT+i];
    __syncthreads();
    if (tid < 112){
        float acc = bt2k[tid];
        for (int i=0;i<NTXT;i++) acc += tx[i]*Wt2k[i*112+tid];
        raw[tid]=acc;
    }
    __syncthreads();
    if (tid < NK){
        int k=tid;
        float mu  = sigmoidf(raw[k*7+0]);
        float sig = softplusf(raw[k*7+1])*HSCALE + 1e-3f;
        float amp = softplusf(raw[k*7+2]);
        float s3=raw[k*7+3], s4=raw[k*7+4], s5=raw[k*7+5], s6=raw[k*7+6];
        float mx=fmaxf(fmaxf(s3,s4),fmaxf(s5,s6));
        float e3=expf(s3-mx),e4=expf(s4-mx),e5=expf(s5-mx),e6=expf(s6-mx);
        float es=e3+e4+e5+e6;
        sws[k][0]=e3/es; sws[k][1]=e4/es; sws[k][2]=e5/es; sws[k][3]=e6/es;
        mus[k]=mu; sigs[k]=sig; amps[k]=amp;
        g_mu[b*NK+k]=mu;
        float ent=0.f;
        #pragma unroll
        for (int s=0;s<4;s++){ float sc=fmaxf(sws[k][s],1e-8f); ent += sc*logf(sc); }
        ent_s[k]=ent;
    }
    __syncthreads();
    for (int k=0;k<NK;k++){
        float mu=mus[k], sig=sigs[k], amp=amps[k];
        float w0=sws[k][0],w1=sws[k][1],w2=sws[k][2],w3=sws[k][3];
        for (int h=tid;h<NH;h+=128){
            float t=(h+0.5f)/(float)NH;
            float z=(t-mu)/sig;
            float az=fabsf(z);
            float b0=expf(-0.5f*z*z);
            float b1=expf(-az);
            float b2=fmaxf(1.f-az,0.f);
            float zc=fminf(fmaxf(z,-1.f),1.f);
            float b3=(az<=1.f)?0.5f*(1.f+cosf(3.14159265358979f*zc)):0.f;
            kap[k][h]=amp*(w0*b0+w1*b1+w2*b2+w3*b3);
        }
    }
    __syncthreads();
    for (int h=tid;h<NH;h+=128){
        float s=0.f;
        #pragma unroll
        for (int k=0;k<NK;k++) s+=kap[k][h];
        g_ytir[b*NH+h]=s;
    }
    if (tid<NK){
        float s=0.f;
        for (int h=0;h<NH;h++) s+=kap[tid][h];
        red[tid]=s+1e-6f;
    }
    __syncthreads();
    if (tid==0){
        float t=0.f; for (int kk=0;kk<NK;kk++) t+=red[kk];
        rtot=t;
        float ent=0.f; for (int kk=0;kk<NK;kk++) ent+=ent_s[kk];
        float tv=0.f;  for (int kk=1;kk<NK;kk++) tv+=fabsf(mus[kk]-mus[kk-1]);
        atomicAdd(&g_acc[3], (double)ent);
        atomicAdd(&g_acc[4], (double)tv);
    }
    __syncthreads();
    if (tid<NK) g_r[b*NK+tid]=red[tid]/rtot;

    // k_emb = kappa @ W_kemb + b (loop-interchanged), then l2-normalize
    int e = tid;  // 128 threads = NEMB
    float acc[NK];
    #pragma unroll
    for (int k=0;k<NK;k++) acc[k]=bkemb[e];
    for (int h=0;h<NH;h++){
        float w = Wkemb[h*NEMB+e];
        #pragma unroll
        for (int k=0;k<NK;k++) acc[k] += kap[k][h]*w;
    }
    __syncthreads();
    float* kemb = &kap[0][0];  // repurpose: 16*128 floats fits in kap
    #pragma unroll
    for (int k=0;k<NK;k++) kemb[k*NEMB+e]=acc[k];
    __syncthreads();
    if (tid<NK){
        float s=0.f;
        for (int i=0;i<NEMB;i++){ float v=kemb[tid*NEMB+i]; s+=v*v; }
        red[tid]=1.f/(sqrtf(s)+1e-8f);
    }
    __syncthreads();
    #pragma unroll
    for (int k=0;k<NK;k++) g_kn[(b*NK+k)*NEMB+e]=kemb[k*NEMB+e]*red[k];
}

// ---------------- kB: ts_global = mean over L (high-MLP version) ---------
__global__ void __launch_bounds__(1024) kB(const float* __restrict__ enc){
    int b=blockIdx.x, tid=threadIdx.x;   // 1024 threads
    int d4 = tid & 63, part = tid >> 6;  // 16 parts x 32 rows
    const float4* p = (const float4*)enc + (size_t)b*NL*(ND/4) + d4;
    float4 s = make_float4(0.f,0.f,0.f,0.f);
    #pragma unroll 8
    for (int l=part*32; l<part*32+32; l++){
        float4 v = p[(size_t)l*(ND/4)];
        s.x+=v.x; s.y+=v.y; s.z+=v.z; s.w+=v.w;
    }
    __shared__ float4 sd[1024];
    sd[tid]=s; __syncthreads();
    for (int st=512; st>=64; st>>=1){
        if (tid<st){
            float4 o=sd[tid+st];
            sd[tid].x+=o.x; sd[tid].y+=o.y; sd[tid].z+=o.z; sd[tid].w+=o.w;
        }
        __syncthreads();
    }
    if (tid<64){
        float4 v=sd[tid];
        const float inv = 1.f/(float)NL;
        v.x*=inv; v.y*=inv; v.z*=inv; v.w*=inv;
        ((float4*)g_tsg)[b*64+tid]=v;
    }
}

// ---------------- kC: gate MLP ----------------
__global__ void kC(const float* __restrict__ text, const float* __restrict__ varp,
                   const float* __restrict__ Wg1, const float* __restrict__ bg1,
                   const float* __restrict__ Wg2, const float* __restrict__ bg2){
    int b0=blockIdx.x*4, tid=threadIdx.x;  // 256 threads
    __shared__ float xin[4][1280];
    __shared__ float hid[4][512];
    for (int bb=0;bb<4;bb++){
        int b=b0+bb;
        for (int i=tid;i<ND;i+=256)   xin[bb][i]=g_tsg[b*ND+i];
        for (int i=tid;i<NTXT;i+=256) xin[bb][ND+i]=text[b*NTXT+i];
        for (int i=tid;i<ND;i+=256)   xin[bb][ND+NTXT+i]=varp[i];
    }
    __syncthreads();
    for (int j=tid;j<512;j+=256){
        float a0=bg1[j],a1=a0,a2=a0,a3=a0;
        for (int i=0;i<1280;i++){
            float w=Wg1[i*512+j];
            a0+=xin[0][i]*w; a1+=xin[1][i]*w; a2+=xin[2][i]*w; a3+=xin[3][i]*w;
        }
        hid[0][j]=fmaxf(a0,0.f); hid[1][j]=fmaxf(a1,0.f);
        hid[2][j]=fmaxf(a2,0.f); hid[3][j]=fmaxf(a3,0.f);
    }
    __syncthreads();
    int d=tid;
    float a0=bg2[d],a1=a0,a2=a0,a3=a0;
    for (int j=0;j<512;j++){
        float w=Wg2[j*256+d];
        a0+=hid[0][j]*w; a1+=hid[1][j]*w; a2+=hid[2][j]*w; a3+=hid[3][j]*w;
    }
    g_gate[(b0+0)*ND+d]=sigmoidf(a0);
    g_gate[(b0+1)*ND+d]=sigmoidf(a1);
    g_gate[(b0+2)*ND+d]=sigmoidf(a2);
    g_gate[(b0+3)*ND+d]=sigmoidf(a3);
}

// ---------------- kD: mse loss ----------------
__global__ void kD(const float* __restrict__ yres, const float* __restrict__ yfut,
                   const float* __restrict__ Wtir, const float* __restrict__ btir,
                   const float* __restrict__ varp){
    const float4* yr4=(const float4*)yres; const float4* yf4=(const float4*)yfut;
    const float4* g4 =(const float4*)g_gate;
    const float4* wt4=(const float4*)Wtir; const float4* bt4=(const float4*)btir;
    const float4* vp4=(const float4*)varp;
    float acc=0.f;
    const int total=NB*NH*ND/4;
    for (int i=blockIdx.x*blockDim.x+threadIdx.x; i<total; i+=gridDim.x*blockDim.x){
        int d4 = i % (ND/4);
        int bh = i / (ND/4);
        int h = bh % NH, b = bh / NH;
        float s = g_ytir[b*NH+h];
        float4 yr=yr4[i], yf=yf4[i];
        float4 wt=wt4[d4], bt=bt4[d4], vp=vp4[d4];
        float4 gg=g4[b*(ND/4)+d4];
        float t0=(s*wt.x+bt.x)*vp.x, t1=(s*wt.y+bt.y)*vp.y;
        float t2=(s*wt.z+bt.z)*vp.z, t3=(s*wt.w+bt.w)*vp.w;
        float h0=yr.x+GWV*gg.x*(t0-yr.x), h1=yr.y+GWV*gg.y*(t1-yr.y);
        float h2=yr.z+GWV*gg.z*(t2-yr.z), h3=yr.w+GWV*gg.w*(t3-yr.w);
        float d0=h0-yf.x, d1=h1-yf.y, d2=h2-yf.z, d3=h3-yf.w;
        acc += d0*d0 + d1*d1 + d2*d2 + d3*d3;
    }
    __shared__ float sred[256];
    sred[threadIdx.x]=acc; __syncthreads();
    for (int s=128;s>0;s>>=1){
        if (threadIdx.x<s) sred[threadIdx.x]+=sred[threadIdx.x+s];
        __syncthreads();
    }
    if (threadIdx.x==0) atomicAdd(&g_acc[0],(double)sred[0]);
}

// ---------------- kGEMM: TF32 tensor-core  T = Y[43008x256] @ Wcat[256x384] ------
// BM=128, BN=128, BK=32, 256 threads, 8 warps (wm 0..1, wn 0..3), warp tile 64x32
#define GA_OFF 0          // As: 2 x 128 x 36 floats
#define GB_OFF 9216       // Bs: 2 x 32 x 132 floats
#define GSM_FLOATS (9216+8448)

__device__ __forceinline__ void cpasync16(unsigned dst, const float* src){
    asm volatile("cp.async.ca.shared.global [%0], [%1], 16;\n" :: "r"(dst), "l"(src));
}

__global__ void __launch_bounds__(256) kGEMM(const float* __restrict__ Y){
    extern __shared__ float smb[];
    unsigned smem_u32 = (unsigned)__cvta_generic_to_shared(smb);
    int m0 = blockIdx.x*128, n0 = blockIdx.y*128;
    int tid = threadIdx.x;
    int warp = tid>>5, lane = tid&31;
    int wm = warp & 1, wn = warp >> 1;
    int lr = lane>>2, lc = lane&3;

    float acc[4][4][4];
    #pragma unroll
    for (int a=0;a<4;a++)
      #pragma unroll
      for (int b=0;b<4;b++)
        #pragma unroll
        for (int c=0;c<4;c++) acc[a][b][c]=0.f;

    auto ldtile = [&](int k0, int buf){
        #pragma unroll
        for (int j=0;j<4;j++){
            int i = tid + j*256;
            int r = i>>3, c4 = i&7;
            unsigned dst = smem_u32 + (unsigned)((GA_OFF + buf*4608 + r*36 + c4*4)*4);
            cpasync16(dst, Y + (size_t)(m0+r)*256 + k0 + c4*4);
        }
        #pragma unroll
        for (int j=0;j<4;j++){
            int i = tid + j*256;
            int r = i>>5, c4 = i&31;
            unsigned dst = smem_u32 + (unsigned)((GB_OFF + buf*4224 + r*132 + c4*4)*4);
            cpasync16(dst, g_Wcat + (k0+r)*384 + n0 + c4*4);
        }
        asm volatile("cp.async.commit_group;\n");
    };

    ldtile(0, 0);
    for (int k0=0; k0<8; k0++){
        if (k0<7){ ldtile((k0+1)*32, (k0+1)&1); asm volatile("cp.async.wait_group 1;\n"); }
        else     { asm volatile("cp.async.wait_group 0;\n"); }
        __syncthreads();
        const float* Ab = smb + GA_OFF + (k0&1)*4608;
        const float* Bb = smb + GB_OFF + (k0&1)*4224;
        #pragma unroll
        for (int ks=0;ks<4;ks++){
            unsigned af[4][4], bf[4][2];
            #pragma unroll
            for (int mt=0;mt<4;mt++){
                const float* p = Ab + (wm*64 + mt*16 + lr)*36 + ks*8 + lc;
                af[mt][0]=__float_as_uint(p[0]);
                af[mt][1]=__float_as_uint(p[8*36]);
                af[mt][2]=__float_as_uint(p[4]);
                af[mt][3]=__float_as_uint(p[8*36+4]);
            }
            #pragma unroll
            for (int nt=0;nt<4;nt++){
                const float* p = Bb + (ks*8+lc)*132 + wn*32 + nt*8 + lr;
                bf[nt][0]=__float_as_uint(p[0]);
                bf[nt][1]=__float_as_uint(p[4*132]);
            }
            #pragma unroll
            for (int mt=0;mt<4;mt++)
              #pragma unroll
              for (int nt=0;nt<4;nt++){
                asm volatile(
                  "mma.sync.aligned.m16n8k8.row.col.f32.tf32.tf32.f32 "
                  "{%0,%1,%2,%3},{%4,%5,%6,%7},{%8,%9},{%0,%1,%2,%3};\n"
                  : "+f"(acc[mt][nt][0]),"+f"(acc[mt][nt][1]),
                    "+f"(acc[mt][nt][2]),"+f"(acc[mt][nt][3])
                  : "r"(af[mt][0]),"r"(af[mt][1]),"r"(af[mt][2]),"r"(af[mt][3]),
                    "r"(bf[nt][0]),"r"(bf[nt][1]));
              }
        }
        __syncthreads();
    }
    // epilogue
    #pragma unroll
    for (int mt=0;mt<4;mt++){
        int r = m0 + wm*64 + mt*16 + lr;
        #pragma unroll
        for (int nt=0;nt<4;nt++){
            int c = n0 + wn*32 + nt*8 + 2*lc;
            *(float2*)&g_T[(size_t)r*384 + c]     = make_float2(acc[mt][nt][0],acc[mt][nt][1]);
            *(float2*)&g_T[(size_t)(r+8)*384 + c] = make_float2(acc[mt][nt][2],acc[mt][nt][3]);
        }
    }
}

// ---------------- kF: shift-combine epilogue + row norms ----------------
__global__ void kF(const float* __restrict__ bfp){
    int m=blockIdx.x; int e=threadIdx.x;   // 128 threads
    int b=m/NH, h=m%NH;
    int m1=b*NH + (h>0?h-1:0);
    int m2=b*NH + (h>1?h-2:0);
    float v = g_T[(size_t)m*384+e] - g_T[(size_t)m1*384+128+e] + g_T[(size_t)m2*384+256+e] + bfp[e];
    g_fpos[(size_t)m*NEMB+e]=v;
    float sq=v*v;
    #pragma unroll
    for (int o=16;o>0;o>>=1) sq+=__shfl_down_sync(0xffffffffu,sq,o);
    __shared__ float w[4];
    if ((threadIdx.x&31)==0) w[threadIdx.x>>5]=sq;
    __syncthreads();
    if (threadIdx.x==0){
        float s=w[0]+w[1]+w[2]+w[3];
        g_invn[m]=1.f/(sqrtf(s)+1e-8f);
    }
}

// ---------------- kG: per-batch: C, Sinkhorn, Pi, cot, contrastive -----
__global__ void __launch_bounds__(512) kG(const int* __restrict__ perm){
    int b=blockIdx.x, tid=threadIdx.x;
    extern __shared__ float sm[];
    float* kn   = sm;              // 2048
    float* Csh  = kn+2048;         // 5376
    float* Km   = Csh+5376;        // 5376
    float* ft   = Km+5376;         // 32*129 = 4128
    float* aggp = ft+4128;         // 2048
    float* aggn = aggp+2048;       // 2048
    float* u    = aggn+2048;       // 16
    float* v    = u+16;            // 336
    float* rr   = v+336;           // 16
    float* mus  = rr+16;           // 16
    float* scr  = mus+16;          // 64
    int* permi  = (int*)(scr+64);  // 128

    for (int i=tid;i<NK*NEMB;i+=512) kn[i]=g_kn[b*NK*NEMB+i];
    if (tid<NK){ rr[tid]=g_r[b*NK+tid]; mus[tid]=g_mu[b*NK+tid]; }
    if (tid<NEMB) permi[tid]=perm[tid];
    if (tid<NH) v[tid]=1.f;
    __syncthreads();

    int k    = tid>>5, lane = tid&31;
    int kq   = tid>>7, e    = tid&127;
    int ck   = tid>>5, chh  = tid&31;

    for (int h0=0;h0<NH;h0+=32){
        int hv=min(32,NH-h0);
        for (int i=tid;i<32*128;i+=512){
            int r2=i>>7, c=i&127;
            if (r2<hv) ft[r2*129+c]=g_fpos[((size_t)(b*NH+h0+r2))*NEMB+c];
        }
        __syncthreads();
        if (chh<hv){
            int h=h0+chh;
            float s=0.f;
            const float* knk=&kn[ck*128];
            const float* fr=&ft[chh*129];
            #pragma unroll 8
            for (int ee=0;ee<128;ee++) s+=knk[ee]*fr[ee];
            float cosv = s*g_invn[b*NH+h];
            float t=(h+0.5f)/(float)NH;
            float C = ALPHAV*(1.f-cosv) + BETAV*fmaxf(mus[ck]-t,0.f);
            Csh[ck*NH+h]=C;
            Km[ck*NH+h]=expf(-C*(1.f/EPSV));
        }
        __syncthreads();
    }

    for (int it=0; it<NITERS; it++){
        {
            float s=0.f;
            for (int h=lane;h<NH;h+=32) s+=Km[k*NH+h]*v[h];
            #pragma unroll
            for (int o=16;o>0;o>>=1) s+=__shfl_down_sync(0xffffffffu,s,o);
            if (lane==0) u[k]=rr[k]/(s+1e-9f);
        }
        __syncthreads();
        if (tid<NH){
            float s=0.f;
            #pragma unroll
            for (int kk=0;kk<NK;kk++) s+=Km[kk*NH+tid]*u[kk];
            v[tid]=(1.f/(float)NH)/(s+1e-9f);
        }
        __syncthreads();
    }

    float cot=0.f;
    for (int i=tid;i<NK*NH;i+=512){
        int kk=i/NH, h=i%NH;
        float pi=u[kk]*Km[i]*v[h];
        Km[i]=pi;
        cot+=Csh[i]*pi;
    }
    #pragma unroll
    for (int o=16;o>0;o>>=1) cot+=__shfl_down_sync(0xffffffffu,cot,o);
    if (lane==0) scr[k]=cot;
    __syncthreads();
    if (tid==0){
        float s=0.f; for (int i=0;i<16;i++) s+=scr[i];
        atomicAdd(&g_acc[1],(double)s);
    }
    {
        float s=0.f;
        for (int h=lane;h<NH;h+=32) s+=Km[k*NH+h];
        #pragma unroll
        for (int o=16;o>0;o>>=1) s+=__shfl_down_sync(0xffffffffu,s,o);
        if (lane==0) scr[16+k]=1.f/(s+1e-9f);
    }
    __syncthreads();
    for (int i=tid;i<NK*NH;i+=512) Km[i]*=scr[16+i/NH];
    __syncthreads();

    float accp[4]={0,0,0,0}, accn[4]={0,0,0,0};
    for (int h0=0;h0<NH;h0+=32){
        int hv=min(32,NH-h0);
        for (int i=tid;i<32*128;i+=512){
            int r2=i>>7, c=i&127;
            if (r2<hv) ft[r2*129+c]=g_fpos[((size_t)(b*NH+h0+r2))*NEMB+c];
        }
        __syncthreads();
        for (int hh=0;hh<hv;hh++){
            float f=ft[hh*129+e];
            int h=h0+hh;
            int hn=h+SHIFT; if (hn>=NH) hn-=NH;
            #pragma unroll
            for (int j=0;j<4;j++){
                int kk=kq*4+j;
                accp[j]+=Km[kk*NH+h ]*f;
                accn[j]+=Km[kk*NH+hn]*f;
            }
        }
        __syncthreads();
    }
    #pragma unroll
    for (int j=0;j<4;j++){
        aggp[(kq*4+j)*128+e]=accp[j];
        aggn[(kq*4+j)*128+e]=accn[j];
    }
    __syncthreads();

    {
        float sp=0,sn=0,dp=0,dn=0,d2=0;
        for (int ee=lane; ee<128; ee+=32){
            float ap=aggp[k*128+ee], an=aggn[k*128+ee], kv=kn[k*128+ee];
            sp+=ap*ap; sn+=an*an; dp+=kv*ap; dn+=kv*an;
            d2+=kv*aggp[k*128+permi[ee]];
        }
        #pragma unroll
        for (int o=16;o>0;o>>=1){
            sp+=__shfl_down_sync(0xffffffffu,sp,o);
            sn+=__shfl_down_sync(0xffffffffu,sn,o);
            dp+=__shfl_down_sync(0xffffffffu,dp,o);
            dn+=__shfl_down_sync(0xffffffffu,dn,o);
            d2+=__shfl_down_sync(0xffffffffu,d2,o);
        }
        if (lane==0){
            float ip=1.f/(sqrtf(sp)+1e-8f), in_=1.f/(sqrtf(sn)+1e-8f);
            float l0=dp*ip*(1.f/TAUV), l1=dn*in_*(1.f/TAUV), l2=d2*ip*(1.f/TAUV);
            float mx=fmaxf(l0,fmaxf(l1,l2));
            float lse=mx+logf(expf(l0-mx)+expf(l1-mx)+expf(l2-mx));
            scr[32+k]=lse-l0;
        }
    }
    __syncthreads();
    if (tid==0){
        float s=0.f; for (int i=0;i<16;i++) s+=scr[32+i];
        atomicAdd(&g_acc[2],(double)s);
    }
}

// ---------------- final combine ----------------
__global__ void kZF(float* out){
    double mse = g_acc[0]/((double)NB*NH*ND);
    double cot = g_acc[1]/(double)NB;
    double del = g_acc[2]/((double)NB*NK);
    double ent = -g_acc[3]/((double)NB*NK);
    double tv  = g_acc[4]/((double)NB*(NK-1));
    out[0]=(float)(1.0*mse + 0.1*cot + 0.1*del + 0.01*ent + 0.01*tv);
}

extern "C" void kernel_launch(void* const* d_in, const int* in_sizes, int n_in,
                              void* d_out, int out_size){
    const float* y_res =(const float*)d_in[0];
    const float* text  =(const float*)d_in[1];
    const float* enc   =(const float*)d_in[2];
    const float* yfut  =(const float*)d_in[3];
    const int*   perm  =(const int*)  d_in[4];
    const float* Wt2k  =(const float*)d_in[5];
    const float* bt2k  =(const float*)d_in[6];
    const float* Wkemb =(const float*)d_in[7];
    const float* bkemb =(const float*)d_in[8];
    const float* Wtir  =(const float*)d_in[9];
    const float* btir  =(const float*)d_in[10];
    const float* varp  =(const float*)d_in[11];
    const float* Wg1   =(const float*)d_in[12];
    const float* bg1   =(const float*)d_in[13];
    const float* Wg2   =(const float*)d_in[14];
    const float* bg2   =(const float*)d_in[15];
    const float* Wfp   =(const float*)d_in[16];
    const float* bfp   =(const float*)d_in[17];
    float* out=(float*)d_out;

    size_t smG = (size_t)(2048+5376+5376+4128+2048+2048+16+336+16+16+64+128)*4;
    size_t smGEMM = (size_t)GSM_FLOATS*4;
    cudaFuncSetAttribute(kG, cudaFuncAttributeMaxDynamicSharedMemorySize, (int)(96*1024));
    cudaFuncSetAttribute(kGEMM, cudaFuncAttributeMaxDynamicSharedMemorySize, (int)(80*1024));

    kWcat<<<(256*384+255)/256,256>>>(Wfp);
    kA<<<NB,128>>>(text,Wt2k,bt2k,Wkemb,bkemb);
    kB<<<NB,1024>>>(enc);
    kC<<<NB/4,256>>>(text,varp,Wg1,bg1,Wg2,bg2);
    kD<<<2688,256>>>(y_res,yfut,Wtir,btir,varp);
    kGEMM<<<dim3(336,3),256,smGEMM>>>(yfut);
    kF<<<NB*NH,128>>>(bfp);
    kG<<<NB,512,smG>>>(perm);
    kZF<<<1,1>>>(out);
}

// round 6
// speedup vs baseline: 3.1050x; 1.7610x over previous
#include <cuda_runtime.h>
#include <stdint.h>
#include <math.h>

#define NB 128
#define NL 512
#define ND 256
#define NH 336
#define NTXT 768
#define NK 16
#define NEMB 128
#define HSCALE 0.15f
#define EPSV 0.05f
#define NITERS 30
#define ALPHAV 1.0f
#define BETAV 0.5f
#define GWV 0.5f
#define TAUV 0.07f
#define SHIFT 56   // max(1, H//6)

// ---------------- device scratch ----------------
__device__ __align__(16) float g_ytir[NB*NH];
__device__ __align__(16) float g_r[NB*NK];
__device__ __align__(16) float g_mu[NB*NK];
__device__ __align__(16) float g_kn[NB*NK*NEMB];
__device__ __align__(16) float g_tsg[NB*ND];
__device__ __align__(16) float g_gate[NB*ND];
__device__ __align__(16) float g_hid[NB*512];
__device__ __align__(16) float g_Wg1T[512*1280];
__device__ __align__(16) float g_Wg2T[256*512];
__device__ __align__(16) float g_Wcat[256*384];
__device__ __align__(16) float g_T[(size_t)NB*NH*384];
__device__ __align__(16) float g_fpos[(size_t)NB*NH*NEMB];
__device__ __align__(16) float g_invn[NB*NH];
__device__ double g_acc[8];   // 0:mse 1:cot 2:delta 3:ent 4:tv

__device__ __forceinline__ float softplusf(float x){
    return fmaxf(x,0.f) + log1pf(expf(-fabsf(x)));
}
__device__ __forceinline__ float sigmoidf(float x){
    return 1.f/(1.f+expf(-x));
}

// ---------------- Wcat prep (+ zero accumulators) --------
__global__ void kWcat(const float* __restrict__ Wfp){
    if (blockIdx.x==0 && threadIdx.x<8) g_acc[threadIdx.x]=0.0;
    int idx = blockIdx.x*blockDim.x + threadIdx.x;
    if (idx >= 256*384) return;
    int c = idx/384, j = idx%384;
    float v;
    if (j < 128){ int e=j;     v = Wfp[c*128+e] + Wfp[(256+c)*128+e] + Wfp[(512+c)*128+e]; }
    else if (j < 256){ int e=j-128; v = Wfp[(256+c)*128+e] + 2.f*Wfp[(512+c)*128+e]; }
    else { int e=j-256; v = Wfp[(512+c)*128+e]; }
    g_Wcat[idx] = v;
}

// ---------------- weight transposes for the gate MLP ----------------
__global__ void kT1(const float* __restrict__ W){   // [1280,512] -> g_Wg1T[512,1280]
    __shared__ float t[32][33];
    int j0 = blockIdx.x*32, i0 = blockIdx.y*32;
    int tx = threadIdx.x, ty = threadIdx.y;  // 32 x 8
    #pragma unroll
    for (int r=ty; r<32; r+=8) t[r][tx] = W[(i0+r)*512 + j0+tx];
    __syncthreads();
    #pragma unroll
    for (int r=ty; r<32; r+=8) g_Wg1T[(j0+r)*1280 + i0+tx] = t[tx][r];
}
__global__ void kT2(const float* __restrict__ W){   // [512,256] -> g_Wg2T[256,512]
    __shared__ float t[32][33];
    int j0 = blockIdx.x*32, i0 = blockIdx.y*32;
    int tx = threadIdx.x, ty = threadIdx.y;
    #pragma unroll
    for (int r=ty; r<32; r+=8) t[r][tx] = W[(i0+r)*256 + j0+tx];
    __syncthreads();
    #pragma unroll
    for (int r=ty; r<32; r+=8) g_Wg2T[(j0+r)*512 + i0+tx] = t[tx][r];
}

// ---------------- kA: text->kernels etc --------
__global__ void kA(const float* __restrict__ text, const float* __restrict__ Wt2k,
                   const float* __restrict__ bt2k, const float* __restrict__ Wkemb,
                   const float* __restrict__ bkemb){
    int b = blockIdx.x, tid = threadIdx.x;   // 128 threads
    __shared__ float tx[NTXT];
    __shared__ float raw[112];
    __shared__ float kap[NK][NH];
    __shared__ float mus[NK], sigs[NK], amps[NK], sws[NK][4];
    __shared__ float red[NK], ent_s[NK];
    __shared__ float rtot;

    for (int i=tid;i<NTXT;i+=128) tx[i]=text[b*NTXT+i];
    __syncthreads();
    if (tid < 112){
        float acc = bt2k[tid];
        for (int i=0;i<NTXT;i++) acc += tx[i]*Wt2k[i*112+tid];
        raw[tid]=acc;
    }
    __syncthreads();
    if (tid < NK){
        int k=tid;
        float mu  = sigmoidf(raw[k*7+0]);
        float sig = softplusf(raw[k*7+1])*HSCALE + 1e-3f;
        float amp = softplusf(raw[k*7+2]);
        float s3=raw[k*7+3], s4=raw[k*7+4], s5=raw[k*7+5], s6=raw[k*7+6];
        float mx=fmaxf(fmaxf(s3,s4),fmaxf(s5,s6));
        float e3=expf(s3-mx),e4=expf(s4-mx),e5=expf(s5-mx),e6=expf(s6-mx);
        float es=e3+e4+e5+e6;
        sws[k][0]=e3/es; sws[k][1]=e4/es; sws[k][2]=e5/es; sws[k][3]=e6/es;
        mus[k]=mu; sigs[k]=sig; amps[k]=amp;
        g_mu[b*NK+k]=mu;
        float ent=0.f;
        #pragma unroll
        for (int s=0;s<4;s++){ float sc=fmaxf(sws[k][s],1e-8f); ent += sc*logf(sc); }
        ent_s[k]=ent;
    }
    __syncthreads();
    for (int k=0;k<NK;k++){
        float mu=mus[k], sig=sigs[k], amp=amps[k];
        float w0=sws[k][0],w1=sws[k][1],w2=sws[k][2],w3=sws[k][3];
        for (int h=tid;h<NH;h+=128){
            float t=(h+0.5f)/(float)NH;
            float z=(t-mu)/sig;
            float az=fabsf(z);
            float b0=expf(-0.5f*z*z);
            float b1=expf(-az);
            float b2=fmaxf(1.f-az,0.f);
            float zc=fminf(fmaxf(z,-1.f),1.f);
            float b3=(az<=1.f)?0.5f*(1.f+cosf(3.14159265358979f*zc)):0.f;
            kap[k][h]=amp*(w0*b0+w1*b1+w2*b2+w3*b3);
        }
    }
    __syncthreads();
    for (int h=tid;h<NH;h+=128){
        float s=0.f;
        #pragma unroll
        for (int k=0;k<NK;k++) s+=kap[k][h];
        g_ytir[b*NH+h]=s;
    }
    if (tid<NK){
        float s=0.f;
        for (int h=0;h<NH;h++) s+=kap[tid][h];
        red[tid]=s+1e-6f;
    }
    __syncthreads();
    if (tid==0){
        float t=0.f; for (int kk=0;kk<NK;kk++) t+=red[kk];
        rtot=t;
        float ent=0.f; for (int kk=0;kk<NK;kk++) ent+=ent_s[kk];
        float tv=0.f;  for (int kk=1;kk<NK;kk++) tv+=fabsf(mus[kk]-mus[kk-1]);
        atomicAdd(&g_acc[3], (double)ent);
        atomicAdd(&g_acc[4], (double)tv);
    }
    __syncthreads();
    if (tid<NK) g_r[b*NK+tid]=red[tid]/rtot;

    // k_emb = kappa @ W_kemb + b (loop-interchanged), then l2-normalize
    int e = tid;  // 128 threads = NEMB
    float acc[NK];
    #pragma unroll
    for (int k=0;k<NK;k++) acc[k]=bkemb[e];
    for (int h=0;h<NH;h++){
        float w = Wkemb[h*NEMB+e];
        #pragma unroll
        for (int k=0;k<NK;k++) acc[k] += kap[k][h]*w;
    }
    __syncthreads();
    float* kemb = &kap[0][0];  // repurpose
    #pragma unroll
    for (int k=0;k<NK;k++) kemb[k*NEMB+e]=acc[k];
    __syncthreads();
    if (tid<NK){
        float s=0.f;
        for (int i=0;i<NEMB;i++){ float v=kemb[tid*NEMB+i]; s+=v*v; }
        red[tid]=1.f/(sqrtf(s)+1e-8f);
    }
    __syncthreads();
    #pragma unroll
    for (int k=0;k<NK;k++) g_kn[(b*NK+k)*NEMB+e]=kemb[k*NEMB+e]*red[k];
}

// ---------------- kB: ts_global = mean over L ---------
__global__ void __launch_bounds__(1024) kB(const float* __restrict__ enc){
    int b=blockIdx.x, tid=threadIdx.x;   // 1024 threads
    int d4 = tid & 63, part = tid >> 6;  // 16 parts x 32 rows
    const float4* p = (const float4*)enc + (size_t)b*NL*(ND/4) + d4;
    float4 s = make_float4(0.f,0.f,0.f,0.f);
    #pragma unroll 8
    for (int l=part*32; l<part*32+32; l++){
        float4 v = p[(size_t)l*(ND/4)];
        s.x+=v.x; s.y+=v.y; s.z+=v.z; s.w+=v.w;
    }
    __shared__ float4 sd[1024];
    sd[tid]=s; __syncthreads();
    for (int st=512; st>=64; st>>=1){
        if (tid<st){
            float4 o=sd[tid+st];
            sd[tid].x+=o.x; sd[tid].y+=o.y; sd[tid].z+=o.z; sd[tid].w+=o.w;
        }
        __syncthreads();
    }
    if (tid<64){
        float4 v=sd[tid];
        const float inv = 1.f/(float)NL;
        v.x*=inv; v.y*=inv; v.z*=inv; v.w*=inv;
        ((float4*)g_tsg)[b*64+tid]=v;
    }
}

// ---------------- kC1: hidden = relu(X @ Wg1 + bg1), warp per output ----------------
__global__ void __launch_bounds__(256) kC1(const float* __restrict__ text,
                                           const float* __restrict__ varp,
                                           const float* __restrict__ bg1){
    int gid = blockIdx.x*8 + (threadIdx.x>>5);   // 65536 warps
    int lane = threadIdx.x & 31;
    int b = gid >> 9, j = gid & 511;
    const float4* Wt = (const float4*)(g_Wg1T + j*1280);
    float acc = 0.f;
    #pragma unroll
    for (int it=0; it<10; it++){
        int i4 = it*32 + lane;
        float4 x;
        if (i4 < 64)        x = ((const float4*)g_tsg)[b*64 + i4];
        else if (i4 < 256)  x = ((const float4*)text)[b*192 + (i4-64)];
        else                x = ((const float4*)varp)[i4-256];
        float4 w = Wt[i4];
        acc += x.x*w.x + x.y*w.y + x.z*w.z + x.w*w.w;
    }
    #pragma unroll
    for (int o=16;o>0;o>>=1) acc += __shfl_down_sync(0xffffffffu, acc, o);
    if (lane==0) g_hid[b*512+j] = fmaxf(acc + bg1[j], 0.f);
}

// ---------------- kC2: gate = sigmoid(hid @ Wg2 + bg2), warp per output ------------
__global__ void __launch_bounds__(256) kC2(const float* __restrict__ bg2){
    int gid = blockIdx.x*8 + (threadIdx.x>>5);   // 32768 warps
    int lane = threadIdx.x & 31;
    int b = gid >> 8, d = gid & 255;
    const float4* Wt = (const float4*)(g_Wg2T + d*512);
    const float4* Hb = (const float4*)(g_hid + b*512);
    float acc = 0.f;
    #pragma unroll
    for (int it=0; it<4; it++){
        int i4 = it*32 + lane;
        float4 h = Hb[i4];
        float4 w = Wt[i4];
        acc += h.x*w.x + h.y*w.y + h.z*w.z + h.w*w.w;
    }
    #pragma unroll
    for (int o=16;o>0;o>>=1) acc += __shfl_down_sync(0xffffffffu, acc, o);
    if (lane==0) g_gate[b*256+d] = sigmoidf(acc + bg2[d]);
}

// ---------------- kD: mse loss ----------------
__global__ void kD(const float* __restrict__ yres, const float* __restrict__ yfut,
                   const float* __restrict__ Wtir, const float* __restrict__ btir,
                   const float* __restrict__ varp){
    const float4* yr4=(const float4*)yres; const float4* yf4=(const float4*)yfut;
    const float4* g4 =(const float4*)g_gate;
    const float4* wt4=(const float4*)Wtir; const float4* bt4=(const float4*)btir;
    const float4* vp4=(const float4*)varp;
    float acc=0.f;
    const int total=NB*NH*ND/4;
    for (int i=blockIdx.x*blockDim.x+threadIdx.x; i<total; i+=gridDim.x*blockDim.x){
        int d4 = i % (ND/4);
        int bh = i / (ND/4);
        int h = bh % NH, b = bh / NH;
        float s = g_ytir[b*NH+h];
        float4 yr=yr4[i], yf=yf4[i];
        float4 wt=wt4[d4], bt=bt4[d4], vp=vp4[d4];
        float4 gg=g4[b*(ND/4)+d4];
        float t0=(s*wt.x+bt.x)*vp.x, t1=(s*wt.y+bt.y)*vp.y;
        float t2=(s*wt.z+bt.z)*vp.z, t3=(s*wt.w+bt.w)*vp.w;
        float h0=yr.x+GWV*gg.x*(t0-yr.x), h1=yr.y+GWV*gg.y*(t1-yr.y);
        float h2=yr.z+GWV*gg.z*(t2-yr.z), h3=yr.w+GWV*gg.w*(t3-yr.w);
        float d0=h0-yf.x, d1=h1-yf.y, d2=h2-yf.z, d3=h3-yf.w;
        acc += d0*d0 + d1*d1 + d2*d2 + d3*d3;
    }
    __shared__ float sred[256];
    sred[threadIdx.x]=acc; __syncthreads();
    for (int s=128;s>0;s>>=1){
        if (threadIdx.x<s) sred[threadIdx.x]+=sred[threadIdx.x+s];
        __syncthreads();
    }
    if (threadIdx.x==0) atomicAdd(&g_acc[0],(double)sred[0]);
}

// ---------------- kGEMM: TF32 tensor-core  T = Y[43008x256] @ Wcat[256x384] ------
#define GA_OFF 0
#define GB_OFF 9216
#define GSM_FLOATS (9216+8448)

__device__ __forceinline__ void cpasync16(unsigned dst, const float* src){
    asm volatile("cp.async.ca.shared.global [%0], [%1], 16;\n" :: "r"(dst), "l"(src));
}

__global__ void __launch_bounds__(256) kGEMM(const float* __restrict__ Y){
    extern __shared__ float smb[];
    unsigned smem_u32 = (unsigned)__cvta_generic_to_shared(smb);
    int m0 = blockIdx.x*128, n0 = blockIdx.y*128;
    int tid = threadIdx.x;
    int warp = tid>>5, lane = tid&31;
    int wm = warp & 1, wn = warp >> 1;
    int lr = lane>>2, lc = lane&3;

    float acc[4][4][4];
    #pragma unroll
    for (int a=0;a<4;a++)
      #pragma unroll
      for (int b=0;b<4;b++)
        #pragma unroll
        for (int c=0;c<4;c++) acc[a][b][c]=0.f;

    auto ldtile = [&](int k0, int buf){
        #pragma unroll
        for (int j=0;j<4;j++){
            int i = tid + j*256;
            int r = i>>3, c4 = i&7;
            unsigned dst = smem_u32 + (unsigned)((GA_OFF + buf*4608 + r*36 + c4*4)*4);
            cpasync16(dst, Y + (size_t)(m0+r)*256 + k0 + c4*4);
        }
        #pragma unroll
        for (int j=0;j<4;j++){
            int i = tid + j*256;
            int r = i>>5, c4 = i&31;
            unsigned dst = smem_u32 + (unsigned)((GB_OFF + buf*4224 + r*132 + c4*4)*4);
            cpasync16(dst, g_Wcat + (k0+r)*384 + n0 + c4*4);
        }
        asm volatile("cp.async.commit_group;\n");
    };

    ldtile(0, 0);
    for (int k0=0; k0<8; k0++){
        if (k0<7){ ldtile((k0+1)*32, (k0+1)&1); asm volatile("cp.async.wait_group 1;\n"); }
        else     { asm volatile("cp.async.wait_group 0;\n"); }
        __syncthreads();
        const float* Ab = smb + GA_OFF + (k0&1)*4608;
        const float* Bb = smb + GB_OFF + (k0&1)*4224;
        #pragma unroll
        for (int ks=0;ks<4;ks++){
            unsigned af[4][4], bf[4][2];
            #pragma unroll
            for (int mt=0;mt<4;mt++){
                const float* p = Ab + (wm*64 + mt*16 + lr)*36 + ks*8 + lc;
                af[mt][0]=__float_as_uint(p[0]);
                af[mt][1]=__float_as_uint(p[8*36]);
                af[mt][2]=__float_as_uint(p[4]);
                af[mt][3]=__float_as_uint(p[8*36+4]);
            }
            #pragma unroll
            for (int nt=0;nt<4;nt++){
                const float* p = Bb + (ks*8+lc)*132 + wn*32 + nt*8 + lr;
                bf[nt][0]=__float_as_uint(p[0]);
                bf[nt][1]=__float_as_uint(p[4*132]);
            }
            #pragma unroll
            for (int mt=0;mt<4;mt++)
              #pragma unroll
              for (int nt=0;nt<4;nt++){
                asm volatile(
                  "mma.sync.aligned.m16n8k8.row.col.f32.tf32.tf32.f32 "
                  "{%0,%1,%2,%3},{%4,%5,%6,%7},{%8,%9},{%0,%1,%2,%3};\n"
                  : "+f"(acc[mt][nt][0]),"+f"(acc[mt][nt][1]),
                    "+f"(acc[mt][nt][2]),"+f"(acc[mt][nt][3])
                  : "r"(af[mt][0]),"r"(af[mt][1]),"r"(af[mt][2]),"r"(af[mt][3]),
                    "r"(bf[nt][0]),"r"(bf[nt][1]));
              }
        }
        __syncthreads();
    }
    #pragma unroll
    for (int mt=0;mt<4;mt++){
        int r = m0 + wm*64 + mt*16 + lr;
        #pragma unroll
        for (int nt=0;nt<4;nt++){
            int c = n0 + wn*32 + nt*8 + 2*lc;
            *(float2*)&g_T[(size_t)r*384 + c]     = make_float2(acc[mt][nt][0],acc[mt][nt][1]);
            *(float2*)&g_T[(size_t)(r+8)*384 + c] = make_float2(acc[mt][nt][2],acc[mt][nt][3]);
        }
    }
}

// ---------------- kF: shift-combine epilogue + row norms ----------------
__global__ void kF(const float* __restrict__ bfp){
    int m=blockIdx.x; int e=threadIdx.x;   // 128 threads
    int b=m/NH, h=m%NH;
    int m1=b*NH + (h>0?h-1:0);
    int m2=b*NH + (h>1?h-2:0);
    float v = g_T[(size_t)m*384+e] - g_T[(size_t)m1*384+128+e] + g_T[(size_t)m2*384+256+e] + bfp[e];
    g_fpos[(size_t)m*NEMB+e]=v;
    float sq=v*v;
    #pragma unroll
    for (int o=16;o>0;o>>=1) sq+=__shfl_down_sync(0xffffffffu,sq,o);
    __shared__ float w[4];
    if ((threadIdx.x&31)==0) w[threadIdx.x>>5]=sq;
    __syncthreads();
    if (threadIdx.x==0){
        float s=w[0]+w[1]+w[2]+w[3];
        g_invn[m]=1.f/(sqrtf(s)+1e-8f);
    }
}

// ---------------- kG: per-batch: C, Sinkhorn, Pi, cot, contrastive -----
__global__ void __launch_bounds__(512) kG(const int* __restrict__ perm){
    int b=blockIdx.x, tid=threadIdx.x;
    extern __shared__ float sm[];
    float* kn   = sm;              // 2048
    float* Csh  = kn+2048;         // 5376
    float* Km   = Csh+5376;        // 5376
    float* ft   = Km+5376;         // 32*129 = 4128
    float* aggp = ft+4128;         // 2048
    float* aggn = aggp+2048;       // 2048
    float* u    = aggn+2048;       // 16
    float* v    = u+16;            // 336
    float* rr   = v+336;           // 16
    float* mus  = rr+16;           // 16
    float* scr  = mus+16;          // 64
    int* permi  = (int*)(scr+64);  // 128

    for (int i=tid;i<NK*NEMB;i+=512) kn[i]=g_kn[b*NK*NEMB+i];
    if (tid<NK){ rr[tid]=g_r[b*NK+tid]; mus[tid]=g_mu[b*NK+tid]; }
    if (tid<NEMB) permi[tid]=perm[tid];
    if (tid<NH) v[tid]=1.f;
    __syncthreads();

    int k    = tid>>5, lane = tid&31;
    int kq   = tid>>7, e    = tid&127;
    int ck   = tid>>5, chh  = tid&31;

    for (int h0=0;h0<NH;h0+=32){
        int hv=min(32,NH-h0);
        for (int i=tid;i<32*128;i+=512){
            int r2=i>>7, c=i&127;
            if (r2<hv) ft[r2*129+c]=g_fpos[((size_t)(b*NH+h0+r2))*NEMB+c];
        }
        __syncthreads();
        if (chh<hv){
            int h=h0+chh;
            float s=0.f;
            const float* knk=&kn[ck*128];
            const float* fr=&ft[chh*129];
            #pragma unroll 8
            for (int ee=0;ee<128;ee++) s+=knk[ee]*fr[ee];
            float cosv = s*g_invn[b*NH+h];
            float t=(h+0.5f)/(float)NH;
            float C = ALPHAV*(1.f-cosv) + BETAV*fmaxf(mus[ck]-t,0.f);
            Csh[ck*NH+h]=C;
            Km[ck*NH+h]=expf(-C*(1.f/EPSV));
        }
        __syncthreads();
    }

    for (int it=0; it<NITERS; it++){
        {
            float s=0.f;
            for (int h=lane;h<NH;h+=32) s+=Km[k*NH+h]*v[h];
            #pragma unroll
            for (int o=16;o>0;o>>=1) s+=__shfl_down_sync(0xffffffffu,s,o);
            if (lane==0) u[k]=rr[k]/(s+1e-9f);
        }
        __syncthreads();
        if (tid<NH){
            float s=0.f;
            #pragma unroll
            for (int kk=0;kk<NK;kk++) s+=Km[kk*NH+tid]*u[kk];
            v[tid]=(1.f/(float)NH)/(s+1e-9f);
        }
        __syncthreads();
    }

    float cot=0.f;
    for (int i=tid;i<NK*NH;i+=512){
        int kk=i/NH, h=i%NH;
        float pi=u[kk]*Km[i]*v[h];
        Km[i]=pi;
        cot+=Csh[i]*pi;
    }
    #pragma unroll
    for (int o=16;o>0;o>>=1) cot+=__shfl_down_sync(0xffffffffu,cot,o);
    if (lane==0) scr[k]=cot;
    __syncthreads();
    if (tid==0){
        float s=0.f; for (int i=0;i<16;i++) s+=scr[i];
        atomicAdd(&g_acc[1],(double)s);
    }
    {
        float s=0.f;
        for (int h=lane;h<NH;h+=32) s+=Km[k*NH+h];
        #pragma unroll
        for (int o=16;o>0;o>>=1) s+=__shfl_down_sync(0xffffffffu,s,o);
        if (lane==0) scr[16+k]=1.f/(s+1e-9f);
    }
    __syncthreads();
    for (int i=tid;i<NK*NH;i+=512) Km[i]*=scr[16+i/NH];
    __syncthreads();

    float accp[4]={0,0,0,0}, accn[4]={0,0,0,0};
    for (int h0=0;h0<NH;h0+=32){
        int hv=min(32,NH-h0);
        for (int i=tid;i<32*128;i+=512){
            int r2=i>>7, c=i&127;
            if (r2<hv) ft[r2*129+c]=g_fpos[((size_t)(b*NH+h0+r2))*NEMB+c];
        }
        __syncthreads();
        for (int hh=0;hh<hv;hh++){
            float f=ft[hh*129+e];
            int h=h0+hh;
            int hn=h+SHIFT; if (hn>=NH) hn-=NH;
            #pragma unroll
            for (int j=0;j<4;j++){
                int kk=kq*4+j;
                accp[j]+=Km[kk*NH+h ]*f;
                accn[j]+=Km[kk*NH+hn]*f;
            }
        }
        __syncthreads();
    }
    #pragma unroll
    for (int j=0;j<4;j++){
        aggp[(kq*4+j)*128+e]=accp[j];
        aggn[(kq*4+j)*128+e]=accn[j];
    }
    __syncthreads();

    {
        float sp=0,sn=0,dp=0,dn=0,d2=0;
        for (int ee=lane; ee<128; ee+=32){
            float ap=aggp[k*128+ee], an=aggn[k*128+ee], kv=kn[k*128+ee];
            sp+=ap*ap; sn+=an*an; dp+=kv*ap; dn+=kv*an;
            d2+=kv*aggp[k*128+permi[ee]];
        }
        #pragma unroll
        for (int o=16;o>0;o>>=1){
            sp+=__shfl_down_sync(0xffffffffu,sp,o);
            sn+=__shfl_down_sync(0xffffffffu,sn,o);
            dp+=__shfl_down_sync(0xffffffffu,dp,o);
            dn+=__shfl_down_sync(0xffffffffu,dn,o);
            d2+=__shfl_down_sync(0xffffffffu,d2,o);
        }
        if (lane==0){
            float ip=1.f/(sqrtf(sp)+1e-8f), in_=1.f/(sqrtf(sn)+1e-8f);
            float l0=dp*ip*(1.f/TAUV), l1=dn*in_*(1.f/TAUV), l2=d2*ip*(1.f/TAUV);
            float mx=fmaxf(l0,fmaxf(l1,l2));
            float lse=mx+logf(expf(l0-mx)+expf(l1-mx)+expf(l2-mx));
            scr[32+k]=lse-l0;
        }
    }
    __syncthreads();
    if (tid==0){
        float s=0.f; for (int i=0;i<16;i++) s+=scr[32+i];
        atomicAdd(&g_acc[2],(double)s);
    }
}

// ---------------- final combine ----------------
__global__ void kZF(float* out){
    double mse = g_acc[0]/((double)NB*NH*ND);
    double cot = g_acc[1]/(double)NB;
    double del = g_acc[2]/((double)NB*NK);
    double ent = -g_acc[3]/((double)NB*NK);
    double tv  = g_acc[4]/((double)NB*(NK-1));
    out[0]=(float)(1.0*mse + 0.1*cot + 0.1*del + 0.01*ent + 0.01*tv);
}

extern "C" void kernel_launch(void* const* d_in, const int* in_sizes, int n_in,
                              void* d_out, int out_size){
    const float* y_res =(const float*)d_in[0];
    const float* text  =(const float*)d_in[1];
    const float* enc   =(const float*)d_in[2];
    const float* yfut  =(const float*)d_in[3];
    const int*   perm  =(const int*)  d_in[4];
    const float* Wt2k  =(const float*)d_in[5];
    const float* bt2k  =(const float*)d_in[6];
    const float* Wkemb =(const float*)d_in[7];
    const float* bkemb =(const float*)d_in[8];
    const float* Wtir  =(const float*)d_in[9];
    const float* btir  =(const float*)d_in[10];
    const float* varp  =(const float*)d_in[11];
    const float* Wg1   =(const float*)d_in[12];
    const float* bg1   =(const float*)d_in[13];
    const float* Wg2   =(const float*)d_in[14];
    const float* bg2   =(const float*)d_in[15];
    const float* Wfp   =(const float*)d_in[16];
    const float* bfp   =(const float*)d_in[17];
    float* out=(float*)d_out;

    size_t smG = (size_t)(2048+5376+5376+4128+2048+2048+16+336+16+16+64+128)*4;
    size_t smGEMM = (size_t)GSM_FLOATS*4;
    cudaFuncSetAttribute(kG, cudaFuncAttributeMaxDynamicSharedMemorySize, (int)(96*1024));
    cudaFuncSetAttribute(kGEMM, cudaFuncAttributeMaxDynamicSharedMemorySize, (int)(80*1024));

    kWcat<<<(256*384+255)/256,256>>>(Wfp);
    kT1<<<dim3(16,40),dim3(32,8)>>>(Wg1);
    kT2<<<dim3(8,16),dim3(32,8)>>>(Wg2);
    kA<<<NB,128>>>(text,Wt2k,bt2k,Wkemb,bkemb);
    kB<<<NB,1024>>>(enc);
    kC1<<<8192,256>>>(text,varp,bg1);
    kC2<<<4096,256>>>(bg2);
    kD<<<2688,256>>>(y_res,yfut,Wtir,btir,varp);
    kGEMM<<<dim3(336,3),256,smGEMM>>>(yfut);
    kF<<<NB*NH,128>>>(bfp);
    kG<<<NB,512,smG>>>(perm);
    kZF<<<1,1>>>(out);
}

// round 7
// speedup vs baseline: 3.7405x; 1.2047x over previous
#include <cuda_runtime.h>
#include <stdint.h>
#include <math.h>

#define NB 128
#define NL 512
#define ND 256
#define NH 336
#define NTXT 768
#define NK 16
#define NEMB 128
#define HSCALE 0.15f
#define EPSV 0.05f
#define NITERS 30
#define ALPHAV 1.0f
#define BETAV 0.5f
#define GWV 0.5f
#define TAUV 0.07f
#define SHIFT 56   // max(1, H//6)

// ---------------- device scratch ----------------
__device__ __align__(16) float g_ytir[NB*NH];
__device__ __align__(16) float g_r[NB*NK];
__device__ __align__(16) float g_mu[NB*NK];
__device__ __align__(16) float g_kn[NB*NK*NEMB];
__device__ __align__(16) float g_tsg[NB*ND];
__device__ __align__(16) float g_gate[NB*ND];
__device__ __align__(16) float g_hid[NB*512];
__device__ __align__(16) float g_Wg1T[512*1280];
__device__ __align__(16) float g_Wg2T[256*512];
__device__ __align__(16) float g_Wt2kT[112*768];
__device__ __align__(16) float g_raw[NB*112];
__device__ __align__(16) float g_par[NB*NK*8];
__device__ __align__(16) float g_kap[(size_t)NB*NK*NH];
__device__ __align__(16) float g_Wcat[256*384];
__device__ __align__(16) float g_T[(size_t)NB*NH*384];
__device__ __align__(16) float g_fpos[(size_t)NB*NH*NEMB];
__device__ __align__(16) float g_invn[NB*NH];
__device__ double g_acc[8];   // 0:mse 1:cot 2:delta 3:ent 4:tv

__device__ __forceinline__ float softplusf(float x){
    return fmaxf(x,0.f) + log1pf(__expf(-fabsf(x)));
}
__device__ __forceinline__ float sigmoidf(float x){
    return 1.f/(1.f+__expf(-x));
}

// ---------------- Wcat prep (+ zero accumulators) --------
__global__ void kWcat(const float* __restrict__ Wfp){
    if (blockIdx.x==0 && threadIdx.x<8) g_acc[threadIdx.x]=0.0;
    int idx = blockIdx.x*blockDim.x + threadIdx.x;
    if (idx >= 256*384) return;
    int c = idx/384, j = idx%384;
    float v;
    if (j < 128){ int e=j;     v = Wfp[c*128+e] + Wfp[(256+c)*128+e] + Wfp[(512+c)*128+e]; }
    else if (j < 256){ int e=j-128; v = Wfp[(256+c)*128+e] + 2.f*Wfp[(512+c)*128+e]; }
    else { int e=j-256; v = Wfp[(512+c)*128+e]; }
    g_Wcat[idx] = v;
}

// ---------------- transposes ----------------
__global__ void kT0(const float* __restrict__ W){   // [768,112] -> g_Wt2kT[112,768]
    __shared__ float t[32][33];
    int j0 = blockIdx.x*32, i0 = blockIdx.y*32;
    int tx = threadIdx.x, ty = threadIdx.y;  // 32 x 8
    #pragma unroll
    for (int r=ty; r<32; r+=8)
        if (j0+tx < 112) t[r][tx] = W[(i0+r)*112 + j0+tx];
    __syncthreads();
    #pragma unroll
    for (int r=ty; r<32; r+=8)
        if (j0+r < 112) g_Wt2kT[(j0+r)*768 + i0+tx] = t[tx][r];
}
__global__ void kT1(const float* __restrict__ W){   // [1280,512] -> g_Wg1T[512,1280]
    __shared__ float t[32][33];
    int j0 = blockIdx.x*32, i0 = blockIdx.y*32;
    int tx = threadIdx.x, ty = threadIdx.y;
    #pragma unroll
    for (int r=ty; r<32; r+=8) t[r][tx] = W[(i0+r)*512 + j0+tx];
    __syncthreads();
    #pragma unroll
    for (int r=ty; r<32; r+=8) g_Wg1T[(j0+r)*1280 + i0+tx] = t[tx][r];
}
__global__ void kT2(const float* __restrict__ W){   // [512,256] -> g_Wg2T[256,512]
    __shared__ float t[32][33];
    int j0 = blockIdx.x*32, i0 = blockIdx.y*32;
    int tx = threadIdx.x, ty = threadIdx.y;
    #pragma unroll
    for (int r=ty; r<32; r+=8) t[r][tx] = W[(i0+r)*256 + j0+tx];
    __syncthreads();
    #pragma unroll
    for (int r=ty; r<32; r+=8) g_Wg2T[(j0+r)*512 + i0+tx] = t[tx][r];
}

// ---------------- kA1: raw = text @ Wt2k + b, warp per output ----------------
__global__ void __launch_bounds__(256) kA1(const float* __restrict__ text,
                                           const float* __restrict__ bt2k){
    int gid = blockIdx.x*8 + (threadIdx.x>>5);   // 14336 warps = 128*112
    int lane = threadIdx.x & 31;
    int b = gid/112, j = gid%112;
    const float* tx = text + b*NTXT;
    const float* wc = g_Wt2kT + j*NTXT;
    float acc=0.f;
    #pragma unroll
    for (int it=0; it<24; it++){
        int i = it*32 + lane;
        acc += tx[i]*wc[i];
    }
    #pragma unroll
    for (int o=16;o>0;o>>=1) acc += __shfl_down_sync(0xffffffffu,acc,o);
    if (lane==0) g_raw[b*112+j] = acc + bt2k[j];
}

// ---------------- kA2: per-(b,k) params + ent/tv ----------------
__global__ void __launch_bounds__(256) kA2(){
    int gt = blockIdx.x*256 + threadIdx.x;  // 2048 threads
    int b = gt>>4, k = gt&15;
    const float* raw = g_raw + b*112 + k*7;
    float mu  = sigmoidf(raw[0]);
    float sig = softplusf(raw[1])*HSCALE + 1e-3f;
    float amp = softplusf(raw[2]);
    float s3=raw[3], s4=raw[4], s5=raw[5], s6=raw[6];
    float mx=fmaxf(fmaxf(s3,s4),fmaxf(s5,s6));
    float e3=__expf(s3-mx),e4=__expf(s4-mx),e5=__expf(s5-mx),e6=__expf(s6-mx);
    float es=e3+e4+e5+e6, ies=1.f/es;
    float w0=e3*ies,w1=e4*ies,w2=e5*ies,w3=e6*ies;
    float* p = g_par + gt*8;
    p[0]=mu; p[1]=1.f/sig; p[2]=amp; p[3]=w0; p[4]=w1; p[5]=w2; p[6]=w3;
    g_mu[gt]=mu;
    float ent=0.f;
    { float c0=fmaxf(w0,1e-8f); ent+=c0*__logf(c0);
      float c1=fmaxf(w1,1e-8f); ent+=c1*__logf(c1);
      float c2=fmaxf(w2,1e-8f); ent+=c2*__logf(c2);
      float c3=fmaxf(w3,1e-8f); ent+=c3*__logf(c3); }
    float tv=0.f;
    if (k>0){
        float mup = sigmoidf(g_raw[b*112+(k-1)*7]);
        tv = fabsf(mu-mup);
    }
    __shared__ float se[256], st[256];
    se[threadIdx.x]=ent; st[threadIdx.x]=tv;
    __syncthreads();
    for (int s=128;s>0;s>>=1){
        if (threadIdx.x<s){ se[threadIdx.x]+=se[threadIdx.x+s]; st[threadIdx.x]+=st[threadIdx.x+s]; }
        __syncthreads();
    }
    if (threadIdx.x==0){
        atomicAdd(&g_acc[3],(double)se[0]);
        atomicAdd(&g_acc[4],(double)st[0]);
    }
}

// ---------------- kA3: kappa elementwise ----------------
__global__ void __launch_bounds__(256) kA3(){
    const float invNH = 1.f/(float)NH;
    const int total = NB*NK*NH;
    for (int i=blockIdx.x*256+threadIdx.x; i<total; i+=gridDim.x*256){
        int bk = i/NH, h = i - bk*NH;
        const float* p = g_par + bk*8;
        float t=(h+0.5f)*invNH;
        float z=(t-p[0])*p[1];
        float az=fabsf(z);
        float b0=__expf(-0.5f*z*z);
        float b1=__expf(-az);
        float b2=fmaxf(1.f-az,0.f);
        float b3=(az<=1.f)?0.5f*(1.f+__cosf(3.14159265358979f*z)):0.f;
        g_kap[i]=p[2]*(p[3]*b0+p[4]*b1+p[5]*b2+p[6]*b3);
    }
}

// ---------------- kA3b: y_tir_scalar = sum_k kappa ----------------
__global__ void __launch_bounds__(256) kA3b(){
    int bh = blockIdx.x*256 + threadIdx.x;  // 43008
    if (bh >= NB*NH) return;
    int b = bh/NH, h = bh - b*NH;
    float s=0.f;
    const float* base = g_kap + (size_t)b*NK*NH + h;
    #pragma unroll
    for (int k=0;k<NK;k++) s += base[k*NH];
    g_ytir[bh]=s;
}

// ---------------- kA3c: r raw sums (normalized later in kG) ----------------
__global__ void __launch_bounds__(256) kA3c(){
    int gid = blockIdx.x*8 + (threadIdx.x>>5);  // 2048 warps
    int lane = threadIdx.x & 31;
    const float* row = g_kap + (size_t)gid*NH;
    float s=0.f;
    for (int h=lane; h<NH; h+=32) s += row[h];
    #pragma unroll
    for (int o=16;o>0;o>>=1) s += __shfl_down_sync(0xffffffffu,s,o);
    if (lane==0) g_r[gid] = s + 1e-6f;
}

// ---------------- kA5: kemb = kappa @ Wkemb + b, fused l2-normalize ----------------
__global__ void __launch_bounds__(128) kA5(const float* __restrict__ Wkemb,
                                           const float* __restrict__ bkemb){
    __shared__ float kapS[8*NH];
    __shared__ float kembS[8*NEMB];
    __shared__ float invS[8];
    int b = blockIdx.x, kg0 = blockIdx.y*8;
    int tid = threadIdx.x;
    const float* src = g_kap + ((size_t)b*NK + kg0)*NH;
    for (int i=tid; i<8*NH; i+=128) kapS[i]=src[i];
    __syncthreads();
    int e = tid;
    float acc[8];
    #pragma unroll
    for (int kr=0;kr<8;kr++) acc[kr]=bkemb[e];
    for (int h=0;h<NH;h++){
        float w = Wkemb[h*NEMB+e];
        #pragma unroll
        for (int kr=0;kr<8;kr++) acc[kr] += kapS[kr*NH+h]*w;
    }
    #pragma unroll
    for (int kr=0;kr<8;kr++) kembS[kr*NEMB+e]=acc[kr];
    __syncthreads();
    int warp = tid>>5, lane = tid&31;
    #pragma unroll
    for (int rr=0;rr<2;rr++){
        int kr = warp*2+rr;
        float s=0.f;
        #pragma unroll
        for (int q=0;q<4;q++){ float v=kembS[kr*NEMB+lane+32*q]; s+=v*v; }
        #pragma unroll
        for (int o=16;o>0;o>>=1) s += __shfl_down_sync(0xffffffffu,s,o);
        if (lane==0) invS[kr]=1.f/(sqrtf(s)+1e-8f);
    }
    __syncthreads();
    float* dst = g_kn + ((size_t)b*NK + kg0)*NEMB;
    #pragma unroll
    for (int kr=0;kr<8;kr++) dst[kr*NEMB+e]=kembS[kr*NEMB+e]*invS[kr];
}

// ---------------- kB: ts_global = mean over L ---------
__global__ void __launch_bounds__(1024) kB(const float* __restrict__ enc){
    int b=blockIdx.x, tid=threadIdx.x;
    int d4 = tid & 63, part = tid >> 6;
    const float4* p = (const float4*)enc + (size_t)b*NL*(ND/4) + d4;
    float4 s = make_float4(0.f,0.f,0.f,0.f);
    #pragma unroll 8
    for (int l=part*32; l<part*32+32; l++){
        float4 v = p[(size_t)l*(ND/4)];
        s.x+=v.x; s.y+=v.y; s.z+=v.z; s.w+=v.w;
    }
    __shared__ float4 sd[1024];
    sd[tid]=s; __syncthreads();
    for (int st=512; st>=64; st>>=1){
        if (tid<st){
            float4 o=sd[tid+st];
            sd[tid].x+=o.x; sd[tid].y+=o.y; sd[tid].z+=o.z; sd[tid].w+=o.w;
        }
        __syncthreads();
    }
    if (tid<64){
        float4 v=sd[tid];
        const float inv = 1.f/(float)NL;
        v.x*=inv; v.y*=inv; v.z*=inv; v.w*=inv;
        ((float4*)g_tsg)[b*64+tid]=v;
    }
}

// ---------------- kC1: hidden = relu(X @ Wg1 + bg1), warp per output ----------------
__global__ void __launch_bounds__(256) kC1(const float* __restrict__ text,
                                           const float* __restrict__ varp,
                                           const float* __restrict__ bg1){
    int gid = blockIdx.x*8 + (threadIdx.x>>5);
    int lane = threadIdx.x & 31;
    int b = gid >> 9, j = gid & 511;
    const float4* Wt = (const float4*)(g_Wg1T + j*1280);
    float acc = 0.f;
    #pragma unroll
    for (int it=0; it<10; it++){
        int i4 = it*32 + lane;
        float4 x;
        if (i4 < 64)        x = ((const float4*)g_tsg)[b*64 + i4];
        else if (i4 < 256)  x = ((const float4*)text)[b*192 + (i4-64)];
        else                x = ((const float4*)varp)[i4-256];
        float4 w = Wt[i4];
        acc += x.x*w.x + x.y*w.y + x.z*w.z + x.w*w.w;
    }
    #pragma unroll
    for (int o=16;o>0;o>>=1) acc += __shfl_down_sync(0xffffffffu, acc, o);
    if (lane==0) g_hid[b*512+j] = fmaxf(acc + bg1[j], 0.f);
}

// ---------------- kC2: gate = sigmoid(hid @ Wg2 + bg2), warp per output ------------
__global__ void __launch_bounds__(256) kC2(const float* __restrict__ bg2){
    int gid = blockIdx.x*8 + (threadIdx.x>>5);
    int lane = threadIdx.x & 31;
    int b = gid >> 8, d = gid & 255;
    const float4* Wt = (const float4*)(g_Wg2T + d*512);
    const float4* Hb = (const float4*)(g_hid + b*512);
    float acc = 0.f;
    #pragma unroll
    for (int it=0; it<4; it++){
        int i4 = it*32 + lane;
        float4 h = Hb[i4];
        float4 w = Wt[i4];
        acc += h.x*w.x + h.y*w.y + h.z*w.z + h.w*w.w;
    }
    #pragma unroll
    for (int o=16;o>0;o>>=1) acc += __shfl_down_sync(0xffffffffu, acc, o);
    if (lane==0) g_gate[b*256+d] = sigmoidf(acc + bg2[d]);
}

// ---------------- kD: mse loss ----------------
__global__ void kD(const float* __restrict__ yres, const float* __restrict__ yfut,
                   const float* __restrict__ Wtir, const float* __restrict__ btir,
                   const float* __restrict__ varp){
    const float4* yr4=(const float4*)yres; const float4* yf4=(const float4*)yfut;
    const float4* g4 =(const float4*)g_gate;
    const float4* wt4=(const float4*)Wtir; const float4* bt4=(const float4*)btir;
    const float4* vp4=(const float4*)varp;
    float acc=0.f;
    const int total=NB*NH*ND/4;
    for (int i=blockIdx.x*blockDim.x+threadIdx.x; i<total; i+=gridDim.x*blockDim.x){
        int d4 = i % (ND/4);
        int bh = i / (ND/4);
        int h = bh % NH, b = bh / NH;
        float s = g_ytir[b*NH+h];
        float4 yr=yr4[i], yf=yf4[i];
        float4 wt=wt4[d4], bt=bt4[d4], vp=vp4[d4];
        float4 gg=g4[b*(ND/4)+d4];
        float t0=(s*wt.x+bt.x)*vp.x, t1=(s*wt.y+bt.y)*vp.y;
        float t2=(s*wt.z+bt.z)*vp.z, t3=(s*wt.w+bt.w)*vp.w;
        float h0=yr.x+GWV*gg.x*(t0-yr.x), h1=yr.y+GWV*gg.y*(t1-yr.y);
        float h2=yr.z+GWV*gg.z*(t2-yr.z), h3=yr.w+GWV*gg.w*(t3-yr.w);
        float d0=h0-yf.x, d1=h1-yf.y, d2=h2-yf.z, d3=h3-yf.w;
        acc += d0*d0 + d1*d1 + d2*d2 + d3*d3;
    }
    __shared__ float sred[256];
    sred[threadIdx.x]=acc; __syncthreads();
    for (int s=128;s>0;s>>=1){
        if (threadIdx.x<s) sred[threadIdx.x]+=sred[threadIdx.x+s];
        __syncthreads();
    }
    if (threadIdx.x==0) atomicAdd(&g_acc[0],(double)sred[0]);
}

// ---------------- kGEMM: TF32 tensor-core  T = Y[43008x256] @ Wcat[256x384] ------
#define GA_OFF 0
#define GB_OFF 9216
#define GSM_FLOATS (9216+8448)

__device__ __forceinline__ void cpasync16(unsigned dst, const float* src){
    asm volatile("cp.async.ca.shared.global [%0], [%1], 16;\n" :: "r"(dst), "l"(src));
}

__global__ void __launch_bounds__(256) kGEMM(const float* __restrict__ Y){
    extern __shared__ float smb[];
    unsigned smem_u32 = (unsigned)__cvta_generic_to_shared(smb);
    int m0 = blockIdx.x*128, n0 = blockIdx.y*128;
    int tid = threadIdx.x;
    int warp = tid>>5, lane = tid&31;
    int wm = warp & 1, wn = warp >> 1;
    int lr = lane>>2, lc = lane&3;

    float acc[4][4][4];
    #pragma unroll
    for (int a=0;a<4;a++)
      #pragma unroll
      for (int b=0;b<4;b++)
        #pragma unroll
        for (int c=0;c<4;c++) acc[a][b][c]=0.f;

    auto ldtile = [&](int k0, int buf){
        #pragma unroll
        for (int j=0;j<4;j++){
            int i = tid + j*256;
            int r = i>>3, c4 = i&7;
            unsigned dst = smem_u32 + (unsigned)((GA_OFF + buf*4608 + r*36 + c4*4)*4);
            cpasync16(dst, Y + (size_t)(m0+r)*256 + k0 + c4*4);
        }
        #pragma unroll
        for (int j=0;j<4;j++){
            int i = tid + j*256;
            int r = i>>5, c4 = i&31;
            unsigned dst = smem_u32 + (unsigned)((GB_OFF + buf*4224 + r*132 + c4*4)*4);
            cpasync16(dst, g_Wcat + (k0+r)*384 + n0 + c4*4);
        }
        asm volatile("cp.async.commit_group;\n");
    };

    ldtile(0, 0);
    for (int k0=0; k0<8; k0++){
        if (k0<7){ ldtile((k0+1)*32, (k0+1)&1); asm volatile("cp.async.wait_group 1;\n"); }
        else     { asm volatile("cp.async.wait_group 0;\n"); }
        __syncthreads();
        const float* Ab = smb + GA_OFF + (k0&1)*4608;
        const float* Bb = smb + GB_OFF + (k0&1)*4224;
        #pragma unroll
        for (int ks=0;ks<4;ks++){
            unsigned af[4][4], bf[4][2];
            #pragma unroll
            for (int mt=0;mt<4;mt++){
                const float* p = Ab + (wm*64 + mt*16 + lr)*36 + ks*8 + lc;
                af[mt][0]=__float_as_uint(p[0]);
                af[mt][1]=__float_as_uint(p[8*36]);
                af[mt][2]=__float_as_uint(p[4]);
                af[mt][3]=__float_as_uint(p[8*36+4]);
            }
            #pragma unroll
            for (int nt=0;nt<4;nt++){
                const float* p = Bb + (ks*8+lc)*132 + wn*32 + nt*8 + lr;
                bf[nt][0]=__float_as_uint(p[0]);
                bf[nt][1]=__float_as_uint(p[4*132]);
            }
            #pragma unroll
            for (int mt=0;mt<4;mt++)
              #pragma unroll
              for (int nt=0;nt<4;nt++){
                asm volatile(
                  "mma.sync.aligned.m16n8k8.row.col.f32.tf32.tf32.f32 "
                  "{%0,%1,%2,%3},{%4,%5,%6,%7},{%8,%9},{%0,%1,%2,%3};\n"
                  : "+f"(acc[mt][nt][0]),"+f"(acc[mt][nt][1]),
                    "+f"(acc[mt][nt][2]),"+f"(acc[mt][nt][3])
                  : "r"(af[mt][0]),"r"(af[mt][1]),"r"(af[mt][2]),"r"(af[mt][3]),
                    "r"(bf[nt][0]),"r"(bf[nt][1]));
              }
        }
        __syncthreads();
    }
    #pragma unroll
    for (int mt=0;mt<4;mt++){
        int r = m0 + wm*64 + mt*16 + lr;
        #pragma unroll
        for (int nt=0;nt<4;nt++){
            int c = n0 + wn*32 + nt*8 + 2*lc;
            *(float2*)&g_T[(size_t)r*384 + c]     = make_float2(acc[mt][nt][0],acc[mt][nt][1]);
            *(float2*)&g_T[(size_t)(r+8)*384 + c] = make_float2(acc[mt][nt][2],acc[mt][nt][3]);
        }
    }
}

// ---------------- kF: shift-combine epilogue + row norms ----------------
__global__ void kF(const float* __restrict__ bfp){
    int m=blockIdx.x; int e=threadIdx.x;   // 128 threads
    int b=m/NH, h=m%NH;
    int m1=b*NH + (h>0?h-1:0);
    int m2=b*NH + (h>1?h-2:0);
    float v = g_T[(size_t)m*384+e] - g_T[(size_t)m1*384+128+e] + g_T[(size_t)m2*384+256+e] + bfp[e];
    g_fpos[(size_t)m*NEMB+e]=v;
    float sq=v*v;
    #pragma unroll
    for (int o=16;o>0;o>>=1) sq+=__shfl_down_sync(0xffffffffu,sq,o);
    __shared__ float w[4];
    if ((threadIdx.x&31)==0) w[threadIdx.x>>5]=sq;
    __syncthreads();
    if (threadIdx.x==0){
        float s=w[0]+w[1]+w[2]+w[3];
        g_invn[m]=1.f/(sqrtf(s)+1e-8f);
    }
}

// ---------------- kG: per-batch: C, Sinkhorn, Pi, cot, contrastive -----
__global__ void __launch_bounds__(512) kG(const int* __restrict__ perm){
    int b=blockIdx.x, tid=threadIdx.x;
    extern __shared__ float sm[];
    float* kn   = sm;              // 2048
    float* Csh  = kn+2048;         // 5376
    float* Km   = Csh+5376;        // 5376
    float* ft   = Km+5376;         // 32*129 = 4128
    float* aggp = ft+4128;         // 2048
    float* aggn = aggp+2048;       // 2048
    float* u    = aggn+2048;       // 16
    float* v    = u+16;            // 336
    float* rr   = v+336;           // 16
    float* mus  = rr+16;           // 16
    float* scr  = mus+16;          // 64
    int* permi  = (int*)(scr+64);  // 128

    for (int i=tid;i<NK*NEMB;i+=512) kn[i]=g_kn[b*NK*NEMB+i];
    if (tid<NK){ rr[tid]=g_r[b*NK+tid]; mus[tid]=g_mu[b*NK+tid]; }
    if (tid<NEMB) permi[tid]=perm[tid];
    if (tid<NH) v[tid]=1.f;
    __syncthreads();
    if (tid==0){
        float t=0.f;
        #pragma unroll
        for (int kk=0;kk<NK;kk++) t+=rr[kk];
        scr[63]=1.f/t;
    }
    __syncthreads();
    if (tid<NK) rr[tid]*=scr[63];
    __syncthreads();

    int k    = tid>>5, lane = tid&31;
    int kq   = tid>>7, e    = tid&127;
    int ck   = tid>>5, chh  = tid&31;

    for (int h0=0;h0<NH;h0+=32){
        int hv=min(32,NH-h0);
        for (int i=tid;i<32*128;i+=512){
            int r2=i>>7, c=i&127;
            if (r2<hv) ft[r2*129+c]=g_fpos[((size_t)(b*NH+h0+r2))*NEMB+c];
        }
        __syncthreads();
        if (chh<hv){
            int h=h0+chh;
            float s=0.f;
            const float* knk=&kn[ck*128];
            const float* fr=&ft[chh*129];
            #pragma unroll 8
            for (int ee=0;ee<128;ee++) s+=knk[ee]*fr[ee];
            float cosv = s*g_invn[b*NH+h];
            float t=(h+0.5f)/(float)NH;
            float C = ALPHAV*(1.f-cosv) + BETAV*fmaxf(mus[ck]-t,0.f);
            Csh[ck*NH+h]=C;
            Km[ck*NH+h]=__expf(-C*(1.f/EPSV));
        }
        __syncthreads();
    }

    for (int it=0; it<NITERS; it++){
        {
            float s=0.f;
            for (int h=lane;h<NH;h+=32) s+=Km[k*NH+h]*v[h];
            #pragma unroll
            for (int o=16;o>0;o>>=1) s+=__shfl_down_sync(0xffffffffu,s,o);
            if (lane==0) u[k]=rr[k]/(s+1e-9f);
        }
        __syncthreads();
        if (tid<NH){
            float s=0.f;
            #pragma unroll
            for (int kk=0;kk<NK;kk++) s+=Km[kk*NH+tid]*u[kk];
            v[tid]=(1.f/(float)NH)/(s+1e-9f);
        }
        __syncthreads();
    }

    float cot=0.f;
    for (int i=tid;i<NK*NH;i+=512){
        int kk=i/NH, h=i%NH;
        float pi=u[kk]*Km[i]*v[h];
        Km[i]=pi;
        cot+=Csh[i]*pi;
    }
    #pragma unroll
    for (int o=16;o>0;o>>=1) cot+=__shfl_down_sync(0xffffffffu,cot,o);
    if (lane==0) scr[k]=cot;
    __syncthreads();
    if (tid==0){
        float s=0.f; for (int i=0;i<16;i++) s+=scr[i];
        atomicAdd(&g_acc[1],(double)s);
    }
    {
        float s=0.f;
        for (int h=lane;h<NH;h+=32) s+=Km[k*NH+h];
        #pragma unroll
        for (int o=16;o>0;o>>=1) s+=__shfl_down_sync(0xffffffffu,s,o);
        if (lane==0) scr[16+k]=1.f/(s+1e-9f);
    }
    __syncthreads();
    for (int i=tid;i<NK*NH;i+=512) Km[i]*=scr[16+i/NH];
    __syncthreads();

    float accp[4]={0,0,0,0}, accn[4]={0,0,0,0};
    for (int h0=0;h0<NH;h0+=32){
        int hv=min(32,NH-h0);
        for (int i=tid;i<32*128;i+=512){
            int r2=i>>7, c=i&127;
            if (r2<hv) ft[r2*129+c]=g_fpos[((size_t)(b*NH+h0+r2))*NEMB+c];
        }
        __syncthreads();
        for (int hh=0;hh<hv;hh++){
            float f=ft[hh*129+e];
            int h=h0+hh;
            int hn=h+SHIFT; if (hn>=NH) hn-=NH;
            #pragma unroll
            for (int j=0;j<4;j++){
                int kk=kq*4+j;
                accp[j]+=Km[kk*NH+h ]*f;
                accn[j]+=Km[kk*NH+hn]*f;
            }
        }
        __syncthreads();
    }
    #pragma unroll
    for (int j=0;j<4;j++){
        aggp[(kq*4+j)*128+e]=accp[j];
        aggn[(kq*4+j)*128+e]=accn[j];
    }
    __syncthreads();

    {
        float sp=0,sn=0,dp=0,dn=0,d2=0;
        for (int ee=lane; ee<128; ee+=32){
            float ap=aggp[k*128+ee], an=aggn[k*128+ee], kv=kn[k*128+ee];
            sp+=ap*ap; sn+=an*an; dp+=kv*ap; dn+=kv*an;
            d2+=kv*aggp[k*128+permi[ee]];
        }
        #pragma unroll
        for (int o=16;o>0;o>>=1){
            sp+=__shfl_down_sync(0xffffffffu,sp,o);
            sn+=__shfl_down_sync(0xffffffffu,sn,o);
            dp+=__shfl_down_sync(0xffffffffu,dp,o);
            dn+=__shfl_down_sync(0xffffffffu,dn,o);
            d2+=__shfl_down_sync(0xffffffffu,d2,o);
        }
        if (lane==0){
            float ip=1.f/(sqrtf(sp)+1e-8f), in_=1.f/(sqrtf(sn)+1e-8f);
            float l0=dp*ip*(1.f/TAUV), l1=dn*in_*(1.f/TAUV), l2=d2*ip*(1.f/TAUV);
            float mx=fmaxf(l0,fmaxf(l1,l2));
            float lse=mx+logf(expf(l0-mx)+expf(l1-mx)+expf(l2-mx));
            scr[32+k]=lse-l0;
        }
    }
    __syncthreads();
    if (tid==0){
        float s=0.f; for (int i=0;i<16;i++) s+=scr[32+i];
        atomicAdd(&g_acc[2],(double)s);
    }
}

// ---------------- final combine ----------------
__global__ void kZF(float* out){
    double mse = g_acc[0]/((double)NB*NH*ND);
    double cot = g_acc[1]/(double)NB;
    double del = g_acc[2]/((double)NB*NK);
    double ent = -g_acc[3]/((double)NB*NK);
    double tv  = g_acc[4]/((double)NB*(NK-1));
    out[0]=(float)(1.0*mse + 0.1*cot + 0.1*del + 0.01*ent + 0.01*tv);
}

extern "C" void kernel_launch(void* const* d_in, const int* in_sizes, int n_in,
                              void* d_out, int out_size){
    const float* y_res =(const float*)d_in[0];
    const float* text  =(const float*)d_in[1];
    const float* enc   =(const float*)d_in[2];
    const float* yfut  =(const float*)d_in[3];
    const int*   perm  =(const int*)  d_in[4];
    const float* Wt2k  =(const float*)d_in[5];
    const float* bt2k  =(const float*)d_in[6];
    const float* Wkemb =(const float*)d_in[7];
    const float* bkemb =(const float*)d_in[8];
    const float* Wtir  =(const float*)d_in[9];
    const float* btir  =(const float*)d_in[10];
    const float* varp  =(const float*)d_in[11];
    const float* Wg1   =(const float*)d_in[12];
    const float* bg1   =(const float*)d_in[13];
    const float* Wg2   =(const float*)d_in[14];
    const float* bg2   =(const float*)d_in[15];
    const float* Wfp   =(const float*)d_in[16];
    const float* bfp   =(const float*)d_in[17];
    float* out=(float*)d_out;

    size_t smG = (size_t)(2048+5376+5376+4128+2048+2048+16+336+16+16+64+128)*4;
    size_t smGEMM = (size_t)GSM_FLOATS*4;
    cudaFuncSetAttribute(kG, cudaFuncAttributeMaxDynamicSharedMemorySize, (int)(96*1024));
    cudaFuncSetAttribute(kGEMM, cudaFuncAttributeMaxDynamicSharedMemorySize, (int)(80*1024));

    kWcat<<<(256*384+255)/256,256>>>(Wfp);
    kT0<<<dim3(4,24),dim3(32,8)>>>(Wt2k);
    kT1<<<dim3(16,40),dim3(32,8)>>>(Wg1);
    kT2<<<dim3(8,16),dim3(32,8)>>>(Wg2);
    kA1<<<1792,256>>>(text,bt2k);
    kA2<<<8,256>>>();
    kA3<<<672,256>>>();
    kA3b<<<168,256>>>();
    kA3c<<<256,256>>>();
    kA5<<<dim3(128,2),128>>>(Wkemb,bkemb);
    kB<<<NB,1024>>>(enc);
    kC1<<<8192,256>>>(text,varp,bg1);
    kC2<<<4096,256>>>(bg2);
    kD<<<2688,256>>>(y_res,yfut,Wtir,btir,varp);
    kGEMM<<<dim3(336,3),256,smGEMM>>>(yfut);
    kF<<<NB*NH,128>>>(bfp);
    kG<<<NB,512,smG>>>(perm);
    kZF<<<1,1>>>(out);
}

// round 8
// speedup vs baseline: 3.9438x; 1.0544x over previous
#include <cuda_runtime.h>
#include <cuda_bf16.h>
#include <stdint.h>
#include <math.h>

#define NB 128
#define NL 512
#define ND 256
#define NH 336
#define NTXT 768
#define NK 16
#define NEMB 128
#define HSCALE 0.15f
#define EPSV 0.05f
#define NITERS 30
#define ALPHAV 1.0f
#define BETAV 0.5f
#define GWV 0.5f
#define TAUV 0.07f
#define SHIFT 56   // max(1, H//6)

// ---------------- device scratch ----------------
__device__ __align__(16) float g_ytir[NB*NH];
__device__ __align__(16) float g_r[NB*NK];
__device__ __align__(16) float g_mu[NB*NK];
__device__ __align__(16) float g_kn[NB*NK*NEMB];
__device__ __align__(16) float g_tsg[NB*ND];
__device__ __align__(16) float g_gate[NB*ND];
__device__ __align__(16) float g_hid[NB*512];
__device__ __align__(16) float g_Wg1T[512*1280];
__device__ __align__(16) float g_Wg2T[256*512];
__device__ __align__(16) float g_Wt2kT[112*768];
__device__ __align__(16) float g_raw[NB*112];
__device__ __align__(16) float g_par[NB*NK*8];
__device__ __align__(16) float g_kap[(size_t)NB*NK*NH];
__device__ __align__(16) unsigned g_WcatP[128*384];          // bf16x2, k-pairs packed
__device__ __align__(16) __nv_bfloat16 g_ybf[(size_t)NB*NH*ND];
__device__ __align__(16) float g_T[(size_t)NB*NH*384];
__device__ __align__(16) float g_fpos[(size_t)NB*NH*NEMB];
__device__ __align__(16) float g_invn[NB*NH];
__device__ double g_acc[8];   // 0:mse 1:cot 2:delta 3:ent 4:tv

__device__ __forceinline__ float softplusf(float x){
    return fmaxf(x,0.f) + log1pf(__expf(-fabsf(x)));
}
__device__ __forceinline__ float sigmoidf(float x){
    return 1.f/(1.f+__expf(-x));
}

// ---------------- Wcat prep: packed bf16 pairs (+ zero accumulators) --------
__device__ __forceinline__ float wcat_elem(const float* __restrict__ Wfp, int c, int j){
    if (j < 128)      return Wfp[c*128+j] + Wfp[(256+c)*128+j] + Wfp[(512+c)*128+j];
    else if (j < 256){ int e=j-128; return Wfp[(256+c)*128+e] + 2.f*Wfp[(512+c)*128+e]; }
    else             { int e=j-256; return Wfp[(512+c)*128+e]; }
}
__global__ void kWcat(const float* __restrict__ Wfp){
    if (blockIdx.x==0 && threadIdx.x<8) g_acc[threadIdx.x]=0.0;
    int idx = blockIdx.x*blockDim.x + threadIdx.x;   // 128*384
    if (idx >= 128*384) return;
    int c2 = idx/384, j = idx%384;
    float v0 = wcat_elem(Wfp, 2*c2,   j);
    float v1 = wcat_elem(Wfp, 2*c2+1, j);
    __nv_bfloat162 p = __floats2bfloat162_rn(v0, v1);
    g_WcatP[idx] = *(unsigned*)&p;
}

// ---------------- transposes ----------------
__global__ void kT0(const float* __restrict__ W){   // [768,112] -> g_Wt2kT[112,768]
    __shared__ float t[32][33];
    int j0 = blockIdx.x*32, i0 = blockIdx.y*32;
    int tx = threadIdx.x, ty = threadIdx.y;  // 32 x 8
    #pragma unroll
    for (int r=ty; r<32; r+=8)
        if (j0+tx < 112) t[r][tx] = W[(i0+r)*112 + j0+tx];
    __syncthreads();
    #pragma unroll
    for (int r=ty; r<32; r+=8)
        if (j0+r < 112) g_Wt2kT[(j0+r)*768 + i0+tx] = t[tx][r];
}
__global__ void kT1(const float* __restrict__ W){   // [1280,512] -> g_Wg1T[512,1280]
    __shared__ float t[32][33];
    int j0 = blockIdx.x*32, i0 = blockIdx.y*32;
    int tx = threadIdx.x, ty = threadIdx.y;
    #pragma unroll
    for (int r=ty; r<32; r+=8) t[r][tx] = W[(i0+r)*512 + j0+tx];
    __syncthreads();
    #pragma unroll
    for (int r=ty; r<32; r+=8) g_Wg1T[(j0+r)*1280 + i0+tx] = t[tx][r];
}
__global__ void kT2(const float* __restrict__ W){   // [512,256] -> g_Wg2T[256,512]
    __shared__ float t[32][33];
    int j0 = blockIdx.x*32, i0 = blockIdx.y*32;
    int tx = threadIdx.x, ty = threadIdx.y;
    #pragma unroll
    for (int r=ty; r<32; r+=8) t[r][tx] = W[(i0+r)*256 + j0+tx];
    __syncthreads();
    #pragma unroll
    for (int r=ty; r<32; r+=8) g_Wg2T[(j0+r)*512 + i0+tx] = t[tx][r];
}

// ---------------- kA1: raw = text @ Wt2k + b, warp per output ----------------
__global__ void __launch_bounds__(256) kA1(const float* __restrict__ text,
                                           const float* __restrict__ bt2k){
    int gid = blockIdx.x*8 + (threadIdx.x>>5);   // 14336 warps
    int lane = threadIdx.x & 31;
    int b = gid/112, j = gid%112;
    const float* tx = text + b*NTXT;
    const float* wc = g_Wt2kT + j*NTXT;
    float acc=0.f;
    #pragma unroll
    for (int it=0; it<24; it++){
        int i = it*32 + lane;
        acc += tx[i]*wc[i];
    }
    #pragma unroll
    for (int o=16;o>0;o>>=1) acc += __shfl_down_sync(0xffffffffu,acc,o);
    if (lane==0) g_raw[b*112+j] = acc + bt2k[j];
}

// ---------------- kA2: per-(b,k) params + ent/tv ----------------
__global__ void __launch_bounds__(256) kA2(){
    int gt = blockIdx.x*256 + threadIdx.x;  // 2048 threads
    int b = gt>>4, k = gt&15;
    const float* raw = g_raw + b*112 + k*7;
    float mu  = sigmoidf(raw[0]);
    float sig = softplusf(raw[1])*HSCALE + 1e-3f;
    float amp = softplusf(raw[2]);
    float s3=raw[3], s4=raw[4], s5=raw[5], s6=raw[6];
    float mx=fmaxf(fmaxf(s3,s4),fmaxf(s5,s6));
    float e3=__expf(s3-mx),e4=__expf(s4-mx),e5=__expf(s5-mx),e6=__expf(s6-mx);
    float es=e3+e4+e5+e6, ies=1.f/es;
    float w0=e3*ies,w1=e4*ies,w2=e5*ies,w3=e6*ies;
    float* p = g_par + gt*8;
    p[0]=mu; p[1]=1.f/sig; p[2]=amp; p[3]=w0; p[4]=w1; p[5]=w2; p[6]=w3;
    g_mu[gt]=mu;
    float ent=0.f;
    { float c0=fmaxf(w0,1e-8f); ent+=c0*__logf(c0);
      float c1=fmaxf(w1,1e-8f); ent+=c1*__logf(c1);
      float c2=fmaxf(w2,1e-8f); ent+=c2*__logf(c2);
      float c3=fmaxf(w3,1e-8f); ent+=c3*__logf(c3); }
    float tv=0.f;
    if (k>0){
        float mup = sigmoidf(g_raw[b*112+(k-1)*7]);
        tv = fabsf(mu-mup);
    }
    __shared__ float se[256], st[256];
    se[threadIdx.x]=ent; st[threadIdx.x]=tv;
    __syncthreads();
    for (int s=128;s>0;s>>=1){
        if (threadIdx.x<s){ se[threadIdx.x]+=se[threadIdx.x+s]; st[threadIdx.x]+=st[threadIdx.x+s]; }
        __syncthreads();
    }
    if (threadIdx.x==0){
        atomicAdd(&g_acc[3],(double)se[0]);
        atomicAdd(&g_acc[4],(double)st[0]);
    }
}

// ---------------- kA3: kappa elementwise ----------------
__global__ void __launch_bounds__(256) kA3(){
    const float invNH = 1.f/(float)NH;
    const int total = NB*NK*NH;
    for (int i=blockIdx.x*256+threadIdx.x; i<total; i+=gridDim.x*256){
        int bk = i/NH, h = i - bk*NH;
        const float* p = g_par + bk*8;
        float t=(h+0.5f)*invNH;
        float z=(t-p[0])*p[1];
        float az=fabsf(z);
        float b0=__expf(-0.5f*z*z);
        float b1=__expf(-az);
        float b2=fmaxf(1.f-az,0.f);
        float b3=(az<=1.f)?0.5f*(1.f+__cosf(3.14159265358979f*z)):0.f;
        g_kap[i]=p[2]*(p[3]*b0+p[4]*b1+p[5]*b2+p[6]*b3);
    }
}

// ---------------- kA3b: y_tir_scalar = sum_k kappa ----------------
__global__ void __launch_bounds__(256) kA3b(){
    int bh = blockIdx.x*256 + threadIdx.x;
    if (bh >= NB*NH) return;
    int b = bh/NH, h = bh - b*NH;
    float s=0.f;
    const float* base = g_kap + (size_t)b*NK*NH + h;
    #pragma unroll
    for (int k=0;k<NK;k++) s += base[k*NH];
    g_ytir[bh]=s;
}

// ---------------- kA3c: r raw sums (normalized in kG) ----------------
__global__ void __launch_bounds__(256) kA3c(){
    int gid = blockIdx.x*8 + (threadIdx.x>>5);
    int lane = threadIdx.x & 31;
    const float* row = g_kap + (size_t)gid*NH;
    float s=0.f;
    for (int h=lane; h<NH; h+=32) s += row[h];
    #pragma unroll
    for (int o=16;o>0;o>>=1) s += __shfl_down_sync(0xffffffffu,s,o);
    if (lane==0) g_r[gid] = s + 1e-6f;
}

// ---------------- kA5: kemb = kappa @ Wkemb + b, fused l2-normalize ----------------
__global__ void __launch_bounds__(128) kA5(const float* __restrict__ Wkemb,
                                           const float* __restrict__ bkemb){
    __shared__ float kapS[8*NH];
    __shared__ float kembS[8*NEMB];
    __shared__ float invS[8];
    int b = blockIdx.x, kg0 = blockIdx.y*8;
    int tid = threadIdx.x;
    const float* src = g_kap + ((size_t)b*NK + kg0)*NH;
    for (int i=tid; i<8*NH; i+=128) kapS[i]=src[i];
    __syncthreads();
    int e = tid;
    float acc[8];
    #pragma unroll
    for (int kr=0;kr<8;kr++) acc[kr]=bkemb[e];
    for (int h=0;h<NH;h++){
        float w = Wkemb[h*NEMB+e];
        #pragma unroll
        for (int kr=0;kr<8;kr++) acc[kr] += kapS[kr*NH+h]*w;
    }
    #pragma unroll
    for (int kr=0;kr<8;kr++) kembS[kr*NEMB+e]=acc[kr];
    __syncthreads();
    int warp = tid>>5, lane = tid&31;
    #pragma unroll
    for (int rr=0;rr<2;rr++){
        int kr = warp*2+rr;
        float s=0.f;
        #pragma unroll
        for (int q=0;q<4;q++){ float v=kembS[kr*NEMB+lane+32*q]; s+=v*v; }
        #pragma unroll
        for (int o=16;o>0;o>>=1) s += __shfl_down_sync(0xffffffffu,s,o);
        if (lane==0) invS[kr]=1.f/(sqrtf(s)+1e-8f);
    }
    __syncthreads();
    float* dst = g_kn + ((size_t)b*NK + kg0)*NEMB;
    #pragma unroll
    for (int kr=0;kr<8;kr++) dst[kr*NEMB+e]=kembS[kr*NEMB+e]*invS[kr];
}

// ---------------- kB: ts_global = mean over L ---------
__global__ void __launch_bounds__(1024) kB(const float* __restrict__ enc){
    int b=blockIdx.x, tid=threadIdx.x;
    int d4 = tid & 63, part = tid >> 6;
    const float4* p = (const float4*)enc + (size_t)b*NL*(ND/4) + d4;
    float4 s = make_float4(0.f,0.f,0.f,0.f);
    #pragma unroll 8
    for (int l=part*32; l<part*32+32; l++){
        float4 v = p[(size_t)l*(ND/4)];
        s.x+=v.x; s.y+=v.y; s.z+=v.z; s.w+=v.w;
    }
    __shared__ float4 sd[1024];
    sd[tid]=s; __syncthreads();
    for (int st=512; st>=64; st>>=1){
        if (tid<st){
            float4 o=sd[tid+st];
            sd[tid].x+=o.x; sd[tid].y+=o.y; sd[tid].z+=o.z; sd[tid].w+=o.w;
        }
        __syncthreads();
    }
    if (tid<64){
        float4 v=sd[tid];
        const float inv = 1.f/(float)NL;
        v.x*=inv; v.y*=inv; v.z*=inv; v.w*=inv;
        ((float4*)g_tsg)[b*64+tid]=v;
    }
}

// ---------------- kC1 / kC2: gate MLP ----------------
__global__ void __launch_bounds__(256) kC1(const float* __restrict__ text,
                                           const float* __restrict__ varp,
                                           const float* __restrict__ bg1){
    int gid = blockIdx.x*8 + (threadIdx.x>>5);
    int lane = threadIdx.x & 31;
    int b = gid >> 9, j = gid & 511;
    const float4* Wt = (const float4*)(g_Wg1T + j*1280);
    float acc = 0.f;
    #pragma unroll
    for (int it=0; it<10; it++){
        int i4 = it*32 + lane;
        float4 x;
        if (i4 < 64)        x = ((const float4*)g_tsg)[b*64 + i4];
        else if (i4 < 256)  x = ((const float4*)text)[b*192 + (i4-64)];
        else                x = ((const float4*)varp)[i4-256];
        float4 w = Wt[i4];
        acc += x.x*w.x + x.y*w.y + x.z*w.z + x.w*w.w;
    }
    #pragma unroll
    for (int o=16;o>0;o>>=1) acc += __shfl_down_sync(0xffffffffu, acc, o);
    if (lane==0) g_hid[b*512+j] = fmaxf(acc + bg1[j], 0.f);
}
__global__ void __launch_bounds__(256) kC2(const float* __restrict__ bg2){
    int gid = blockIdx.x*8 + (threadIdx.x>>5);
    int lane = threadIdx.x & 31;
    int b = gid >> 8, d = gid & 255;
    const float4* Wt = (const float4*)(g_Wg2T + d*512);
    const float4* Hb = (const float4*)(g_hid + b*512);
    float acc = 0.f;
    #pragma unroll
    for (int it=0; it<4; it++){
        int i4 = it*32 + lane;
        float4 h = Hb[i4];
        float4 w = Wt[i4];
        acc += h.x*w.x + h.y*w.y + h.z*w.z + h.w*w.w;
    }
    #pragma unroll
    for (int o=16;o>0;o>>=1) acc += __shfl_down_sync(0xffffffffu, acc, o);
    if (lane==0) g_gate[b*256+d] = sigmoidf(acc + bg2[d]);
}

// ---------------- kD: mse loss + y_future -> bf16 ----------------
__global__ void kD(const float* __restrict__ yres, const float* __restrict__ yfut,
                   const float* __restrict__ Wtir, const float* __restrict__ btir,
                   const float* __restrict__ varp){
    const float4* yr4=(const float4*)yres; const float4* yf4=(const float4*)yfut;
    const float4* g4 =(const float4*)g_gate;
    const float4* wt4=(const float4*)Wtir; const float4* bt4=(const float4*)btir;
    const float4* vp4=(const float4*)varp;
    uint2* yb2 = (uint2*)g_ybf;
    float acc=0.f;
    const int total=NB*NH*ND/4;
    for (int i=blockIdx.x*blockDim.x+threadIdx.x; i<total; i+=gridDim.x*blockDim.x){
        int d4 = i % (ND/4);
        int bh = i / (ND/4);
        int h = bh % NH, b = bh / NH;
        float s = g_ytir[b*NH+h];
        float4 yr=yr4[i], yf=yf4[i];
        // bf16 pack of y_future (for the tensor GEMM)
        __nv_bfloat162 p0 = __floats2bfloat162_rn(yf.x, yf.y);
        __nv_bfloat162 p1 = __floats2bfloat162_rn(yf.z, yf.w);
        yb2[i] = make_uint2(*(unsigned*)&p0, *(unsigned*)&p1);
        float4 wt=wt4[d4], bt=bt4[d4], vp=vp4[d4];
        float4 gg=g4[b*(ND/4)+d4];
        float t0=(s*wt.x+bt.x)*vp.x, t1=(s*wt.y+bt.y)*vp.y;
        float t2=(s*wt.z+bt.z)*vp.z, t3=(s*wt.w+bt.w)*vp.w;
        float h0=yr.x+GWV*gg.x*(t0-yr.x), h1=yr.y+GWV*gg.y*(t1-yr.y);
        float h2=yr.z+GWV*gg.z*(t2-yr.z), h3=yr.w+GWV*gg.w*(t3-yr.w);
        float d0=h0-yf.x, d1=h1-yf.y, d2=h2-yf.z, d3=h3-yf.w;
        acc += d0*d0 + d1*d1 + d2*d2 + d3*d3;
    }
    __shared__ float sred[256];
    sred[threadIdx.x]=acc; __syncthreads();
    for (int s=128;s>0;s>>=1){
        if (threadIdx.x<s) sred[threadIdx.x]+=sred[threadIdx.x+s];
        __syncthreads();
    }
    if (threadIdx.x==0) atomicAdd(&g_acc[0],(double)sred[0]);
}

// ---------------- kGEMM: bf16 tensor-core  T = Ybf[43008x256] @ WcatP[256x384] ----
// BM=128, BN=128, BK=32, 256 threads, warp tile 64x32, mma.m16n8k16
// As: bf16 rows padded to 40 bf16 (20 words) -> 128*20=2560 words per buffer
// Bs: packed k-pair words, 16 rows x 136 words -> 2176 words per buffer
#define GA_W 2560
#define GB_BASE 5120
#define GB_W 2176
#define GSM_WORDS (5120+4352)

__device__ __forceinline__ void cpasync16(unsigned dst, const void* src){
    asm volatile("cp.async.ca.shared.global [%0], [%1], 16;\n" :: "r"(dst), "l"(src));
}

__global__ void __launch_bounds__(256) kGEMM(){
    extern __shared__ unsigned smw[];
    unsigned smem_u32 = (unsigned)__cvta_generic_to_shared(smw);
    int m0 = blockIdx.x*128, n0 = blockIdx.y*128;
    int tid = threadIdx.x;
    int warp = tid>>5, lane = tid&31;
    int wm = warp & 1, wn = warp >> 1;
    int lr = lane>>2, lc = lane&3;   // groupID, tig

    float acc[4][4][4];
    #pragma unroll
    for (int a=0;a<4;a++)
      #pragma unroll
      for (int b=0;b<4;b++)
        #pragma unroll
        for (int c=0;c<4;c++) acc[a][b][c]=0.f;

    auto ldtile = [&](int t, int buf){
        int k0 = t*32;          // bf16 k offset
        int k20 = t*16;         // packed-word row offset
        // A tile: 128 rows x 64B = 512 x 16B chunks
        #pragma unroll
        for (int j=0;j<2;j++){
            int i = tid + j*256;
            int r = i>>2, c4 = i&3;
            unsigned dst = smem_u32 + (unsigned)((buf*GA_W + r*20 + c4*4)*4);
            cpasync16(dst, g_ybf + (size_t)(m0+r)*256 + k0 + c4*8);
        }
        // B tile: 16 rows x 128 words = 512 x 16B chunks
        #pragma unroll
        for (int j=0;j<2;j++){
            int i = tid + j*256;
            int r = i>>5, c4 = i&31;
            unsigned dst = smem_u32 + (unsigned)((GB_BASE + buf*GB_W + r*136 + c4*4)*4);
            cpasync16(dst, g_WcatP + (k20+r)*384 + n0 + c4*4);
        }
        asm volatile("cp.async.commit_group;\n");
    };

    ldtile(0, 0);
    for (int t=0; t<8; t++){
        if (t<7){ ldtile(t+1, (t+1)&1); asm volatile("cp.async.wait_group 1;\n"); }
        else    { asm volatile("cp.async.wait_group 0;\n"); }
        __syncthreads();
        const unsigned* Ab = smw + (t&1)*GA_W;
        const unsigned* Bb = smw + GB_BASE + (t&1)*GB_W;
        #pragma unroll
        for (int ks=0;ks<2;ks++){
            unsigned af[4][4], bf[4][2];
            #pragma unroll
            for (int mt=0;mt<4;mt++){
                int r = wm*64 + mt*16 + lr;
                const unsigned* p  = Ab + r*20 + ks*8 + lc;
                const unsigned* p8 = Ab + (r+8)*20 + ks*8 + lc;
                af[mt][0]=p[0]; af[mt][1]=p8[0]; af[mt][2]=p[4]; af[mt][3]=p8[4];
            }
            #pragma unroll
            for (int nt=0;nt<4;nt++){
                int n = wn*32 + nt*8 + lr;
                const unsigned* p = Bb + (ks*8+lc)*136 + n;
                bf[nt][0]=p[0]; bf[nt][1]=p[4*136];
            }
            #pragma unroll
            for (int mt=0;mt<4;mt++)
              #pragma unroll
              for (int nt=0;nt<4;nt++){
                asm volatile(
                  "mma.sync.aligned.m16n8k16.row.col.f32.bf16.bf16.f32 "
                  "{%0,%1,%2,%3},{%4,%5,%6,%7},{%8,%9},{%0,%1,%2,%3};\n"
                  : "+f"(acc[mt][nt][0]),"+f"(acc[mt][nt][1]),
                    "+f"(acc[mt][nt][2]),"+f"(acc[mt][nt][3])
                  : "r"(af[mt][0]),"r"(af[mt][1]),"r"(af[mt][2]),"r"(af[mt][3]),
                    "r"(bf[nt][0]),"r"(bf[nt][1]));
              }
        }
        __syncthreads();
    }
    #pragma unroll
    for (int mt=0;mt<4;mt++){
        int r = m0 + wm*64 + mt*16 + lr;
        #pragma unroll
        for (int nt=0;nt<4;nt++){
            int c = n0 + wn*32 + nt*8 + 2*lc;
            *(float2*)&g_T[(size_t)r*384 + c]     = make_float2(acc[mt][nt][0],acc[mt][nt][1]);
            *(float2*)&g_T[(size_t)(r+8)*384 + c] = make_float2(acc[mt][nt][2],acc[mt][nt][3]);
        }
    }
}

// ---------------- kF: shift-combine epilogue + row norms ----------------
__global__ void kF(const float* __restrict__ bfp){
    int m=blockIdx.x; int e=threadIdx.x;   // 128 threads
    int b=m/NH, h=m%NH;
    int m1=b*NH + (h>0?h-1:0);
    int m2=b*NH + (h>1?h-2:0);
    float v = g_T[(size_t)m*384+e] - g_T[(size_t)m1*384+128+e] + g_T[(size_t)m2*384+256+e] + bfp[e];
    g_fpos[(size_t)m*NEMB+e]=v;
    float sq=v*v;
    #pragma unroll
    for (int o=16;o>0;o>>=1) sq+=__shfl_down_sync(0xffffffffu,sq,o);
    __shared__ float w[4];
    if ((threadIdx.x&31)==0) w[threadIdx.x>>5]=sq;
    __syncthreads();
    if (threadIdx.x==0){
        float s=w[0]+w[1]+w[2]+w[3];
        g_invn[m]=1.f/(sqrtf(s)+1e-8f);
    }
}

// ---------------- kG: per-batch: C, Sinkhorn, Pi, cot, contrastive -----
__global__ void __launch_bounds__(512) kG(const int* __restrict__ perm){
    int b=blockIdx.x, tid=threadIdx.x;
    extern __shared__ float sm[];
    float* kn   = sm;              // 2048
    float* Csh  = kn+2048;         // 5376
    float* Km   = Csh+5376;        // 5376
    float* ft   = Km+5376;         // 4128
    float* aggp = ft+4128;         // 2048
    float* aggn = aggp+2048;       // 2048
    float* u    = aggn+2048;       // 16
    float* v    = u+16;            // 336
    float* rr   = v+336;           // 16
    float* mus  = rr+16;           // 16
    float* scr  = mus+16;          // 64
    int* permi  = (int*)(scr+64);  // 128

    for (int i=tid;i<NK*NEMB;i+=512) kn[i]=g_kn[b*NK*NEMB+i];
    if (tid<NK){ rr[tid]=g_r[b*NK+tid]; mus[tid]=g_mu[b*NK+tid]; }
    if (tid<NEMB) permi[tid]=perm[tid];
    if (tid<NH) v[tid]=1.f;
    __syncthreads();
    if (tid==0){
        float t=0.f;
        #pragma unroll
        for (int kk=0;kk<NK;kk++) t+=rr[kk];
        scr[63]=1.f/t;
    }
    __syncthreads();
    if (tid<NK) rr[tid]*=scr[63];
    __syncthreads();

    int k    = tid>>5, lane = tid&31;
    int kq   = tid>>7, e    = tid&127;
    int ck   = tid>>5, chh  = tid&31;

    for (int h0=0;h0<NH;h0+=32){
        int hv=min(32,NH-h0);
        for (int i=tid;i<32*128;i+=512){
            int r2=i>>7, c=i&127;
            if (r2<hv) ft[r2*129+c]=g_fpos[((size_t)(b*NH+h0+r2))*NEMB+c];
        }
        __syncthreads();
        if (chh<hv){
            int h=h0+chh;
            float s=0.f;
            const float* knk=&kn[ck*128];
            const float* fr=&ft[chh*129];
            #pragma unroll 8
            for (int ee=0;ee<128;ee++) s+=knk[ee]*fr[ee];
            float cosv = s*g_invn[b*NH+h];
            float t=(h+0.5f)/(float)NH;
            float C = ALPHAV*(1.f-cosv) + BETAV*fmaxf(mus[ck]-t,0.f);
            Csh[ck*NH+h]=C;
            Km[ck*NH+h]=__expf(-C*(1.f/EPSV));
        }
        __syncthreads();
    }

    for (int it=0; it<NITERS; it++){
        {
            float s=0.f;
            for (int h=lane;h<NH;h+=32) s+=Km[k*NH+h]*v[h];
            #pragma unroll
            for (int o=16;o>0;o>>=1) s+=__shfl_down_sync(0xffffffffu,s,o);
            if (lane==0) u[k]=rr[k]/(s+1e-9f);
        }
        __syncthreads();
        if (tid<NH){
            float s=0.f;
            #pragma unroll
            for (int kk=0;kk<NK;kk++) s+=Km[kk*NH+tid]*u[kk];
            v[tid]=(1.f/(float)NH)/(s+1e-9f);
        }
        __syncthreads();
    }

    float cot=0.f;
    for (int i=tid;i<NK*NH;i+=512){
        int kk=i/NH, h=i%NH;
        float pi=u[kk]*Km[i]*v[h];
        Km[i]=pi;
        cot+=Csh[i]*pi;
    }
    #pragma unroll
    for (int o=16;o>0;o>>=1) cot+=__shfl_down_sync(0xffffffffu,cot,o);
    if (lane==0) scr[k]=cot;
    __syncthreads();
    if (tid==0){
        float s=0.f; for (int i=0;i<16;i++) s+=scr[i];
        atomicAdd(&g_acc[1],(double)s);
    }
    {
        float s=0.f;
        for (int h=lane;h<NH;h+=32) s+=Km[k*NH+h];
        #pragma unroll
        for (int o=16;o>0;o>>=1) s+=__shfl_down_sync(0xffffffffu,s,o);
        if (lane==0) scr[16+k]=1.f/(s+1e-9f);
    }
    __syncthreads();
    for (int i=tid;i<NK*NH;i+=512) Km[i]*=scr[16+i/NH];
    __syncthreads();

    float accp[4]={0,0,0,0}, accn[4]={0,0,0,0};
    for (int h0=0;h0<NH;h0+=32){
        int hv=min(32,NH-h0);
        for (int i=tid;i<32*128;i+=512){
            int r2=i>>7, c=i&127;
            if (r2<hv) ft[r2*129+c]=g_fpos[((size_t)(b*NH+h0+r2))*NEMB+c];
        }
        __syncthreads();
        for (int hh=0;hh<hv;hh++){
            float f=ft[hh*129+e];
            int h=h0+hh;
            int hn=h+SHIFT; if (hn>=NH) hn-=NH;
            #pragma unroll
            for (int j=0;j<4;j++){
                int kk=kq*4+j;
                accp[j]+=Km[kk*NH+h ]*f;
                accn[j]+=Km[kk*NH+hn]*f;
            }
        }
        __syncthreads();
    }
    #pragma unroll
    for (int j=0;j<4;j++){
        aggp[(kq*4+j)*128+e]=accp[j];
        aggn[(kq*4+j)*128+e]=accn[j];
    }
    __syncthreads();

    {
        float sp=0,sn=0,dp=0,dn=0,d2=0;
        for (int ee=lane; ee<128; ee+=32){
            float ap=aggp[k*128+ee], an=aggn[k*128+ee], kv=kn[k*128+ee];
            sp+=ap*ap; sn+=an*an; dp+=kv*ap; dn+=kv*an;
            d2+=kv*aggp[k*128+permi[ee]];
        }
        #pragma unroll
        for (int o=16;o>0;o>>=1){
            sp+=__shfl_down_sync(0xffffffffu,sp,o);
            sn+=__shfl_down_sync(0xffffffffu,sn,o);
            dp+=__shfl_down_sync(0xffffffffu,dp,o);
            dn+=__shfl_down_sync(0xffffffffu,dn,o);
            d2+=__shfl_down_sync(0xffffffffu,d2,o);
        }
        if (lane==0){
            float ip=1.f/(sqrtf(sp)+1e-8f), in_=1.f/(sqrtf(sn)+1e-8f);
            float l0=dp*ip*(1.f/TAUV), l1=dn*in_*(1.f/TAUV), l2=d2*ip*(1.f/TAUV);
            float mx=fmaxf(l0,fmaxf(l1,l2));
            float lse=mx+logf(expf(l0-mx)+expf(l1-mx)+expf(l2-mx));
            scr[32+k]=lse-l0;
        }
    }
    __syncthreads();
    if (tid==0){
        float s=0.f; for (int i=0;i<16;i++) s+=scr[32+i];
        atomicAdd(&g_acc[2],(double)s);
    }
}

// ---------------- final combine ----------------
__global__ void kZF(float* out){
    double mse = g_acc[0]/((double)NB*NH*ND);
    double cot = g_acc[1]/(double)NB;
    double del = g_acc[2]/((double)NB*NK);
    double ent = -g_acc[3]/((double)NB*NK);
    double tv  = g_acc[4]/((double)NB*(NK-1));
    out[0]=(float)(1.0*mse + 0.1*cot + 0.1*del + 0.01*ent + 0.01*tv);
}

extern "C" void kernel_launch(void* const* d_in, const int* in_sizes, int n_in,
                              void* d_out, int out_size){
    const float* y_res =(const float*)d_in[0];
    const float* text  =(const float*)d_in[1];
    const float* enc   =(const float*)d_in[2];
    const float* yfut  =(const float*)d_in[3];
    const int*   perm  =(const int*)  d_in[4];
    const float* Wt2k  =(const float*)d_in[5];
    const float* bt2k  =(const float*)d_in[6];
    const float* Wkemb =(const float*)d_in[7];
    const float* bkemb =(const float*)d_in[8];
    const float* Wtir  =(const float*)d_in[9];
    const float* btir  =(const float*)d_in[10];
    const float* varp  =(const float*)d_in[11];
    const float* Wg1   =(const float*)d_in[12];
    const float* bg1   =(const float*)d_in[13];
    const float* Wg2   =(const float*)d_in[14];
    const float* bg2   =(const float*)d_in[15];
    const float* Wfp   =(const float*)d_in[16];
    const float* bfp   =(const float*)d_in[17];
    float* out=(float*)d_out;

    size_t smG = (size_t)(2048+5376+5376+4128+2048+2048+16+336+16+16+64+128)*4;
    size_t smGEMM = (size_t)GSM_WORDS*4;
    cudaFuncSetAttribute(kG, cudaFuncAttributeMaxDynamicSharedMemorySize, (int)(96*1024));
    cudaFuncSetAttribute(kGEMM, cudaFuncAttributeMaxDynamicSharedMemorySize, (int)(64*1024));

    kWcat<<<(128*384+255)/256,256>>>(Wfp);
    kT0<<<dim3(4,24),dim3(32,8)>>>(Wt2k);
    kT1<<<dim3(16,40),dim3(32,8)>>>(Wg1);
    kT2<<<dim3(8,16),dim3(32,8)>>>(Wg2);
    kA1<<<1792,256>>>(text,bt2k);
    kA2<<<8,256>>>();
    kA3<<<672,256>>>();
    kA3b<<<168,256>>>();
    kA3c<<<256,256>>>();
    kA5<<<dim3(128,2),128>>>(Wkemb,bkemb);
    kB<<<NB,1024>>>(enc);
    kC1<<<8192,256>>>(text,varp,bg1);
    kC2<<<4096,256>>>(bg2);
    kD<<<2688,256>>>(y_res,yfut,Wtir,btir,varp);
    kGEMM<<<dim3(336,3),256,smGEMM>>>();
    kF<<<NB*NH,128>>>(bfp);
    kG<<<NB,512,smG>>>(perm);
    kZF<<<1,1>>>(out);
}

// round 12
// speedup vs baseline: 4.6264x; 1.1731x over previous
#include <cuda_runtime.h>
#include <cuda_bf16.h>
#include <stdint.h>
#include <math.h>

#define NB 128
#define NL 512
#define ND 256
#define NH 336
#define NTXT 768
#define NK 16
#define NEMB 128
#define HSCALE 0.15f
#define EPSV 0.05f
#define NITERS 30
#define ALPHAV 1.0f
#define BETAV 0.5f
#define GWV 0.5f
#define TAUV 0.07f
#define SHIFT 56   // max(1, H//6)

// ---------------- device scratch ----------------
__device__ __align__(16) float g_ytir[NB*NH];
__device__ __align__(16) float g_r[NB*NK];
__device__ __align__(16) float g_mu[NB*NK];
__device__ __align__(16) float g_kn[NB*NK*NEMB];
__device__ __align__(16) float g_tsg[NB*ND];
__device__ __align__(16) float g_gate[NB*ND];
__device__ __align__(16) float g_hid[NB*512];
__device__ __align__(16) float g_Wg1T[512*1280];
__device__ __align__(16) float g_Wg2T[256*512];
__device__ __align__(16) float g_Wt2kT[112*768];
__device__ __align__(16) float g_raw[NB*112];
__device__ __align__(16) float g_par[NB*NK*8];
__device__ __align__(16) float g_kap[(size_t)NB*NK*NH];
__device__ __align__(16) unsigned g_WcatP[128*384];
__device__ __align__(16) __nv_bfloat16 g_ybf[(size_t)NB*NH*ND];
__device__ __align__(16) float g_T[(size_t)NB*NH*384];
__device__ __align__(16) float g_fpos[(size_t)NB*NH*NEMB];
__device__ __align__(16) float g_invn[NB*NH];
__device__ double g_acc[8];   // 0:mse 1:cot 2:delta 3:ent 4:tv

__device__ __forceinline__ float softplusf(float x){
    return fmaxf(x,0.f) + log1pf(__expf(-fabsf(x)));
}
__device__ __forceinline__ float sigmoidf(float x){
    return 1.f/(1.f+__expf(-x));
}
__device__ __forceinline__ float wcat_elem(const float* __restrict__ Wfp, int c, int j){
    if (j < 128)      return Wfp[c*128+j] + Wfp[(256+c)*128+j] + Wfp[(512+c)*128+j];
    else if (j < 256){ int e=j-128; return Wfp[(256+c)*128+e] + 2.f*Wfp[(512+c)*128+e]; }
    else             { int e=j-256; return Wfp[(512+c)*128+e]; }
}

// =============== P1: Wcat pack + transposes + ybf + kB + zero ===============
// blocks: [0,192) Wcat | [192,288) T0 | [288,928) T1 | [928,1056) T2
//         [1056,2400) ybf | [2400,2528) kB
__global__ void __launch_bounds__(256) kP1(const float* __restrict__ Wfp,
        const float* __restrict__ Wt2k, const float* __restrict__ Wg1,
        const float* __restrict__ Wg2, const float* __restrict__ yfut,
        const float* __restrict__ enc){
    __shared__ float t[32][33];
    __shared__ float4 sd[256];
    int bid = blockIdx.x, tid = threadIdx.x;
    if (bid==0 && tid<8) g_acc[tid]=0.0;
    if (bid < 192){
        int idx = bid*256+tid;  // exactly 128*384
        int c2 = idx/384, j = idx%384;
        float v0 = wcat_elem(Wfp, 2*c2,   j);
        float v1 = wcat_elem(Wfp, 2*c2+1, j);
        __nv_bfloat162 p = __floats2bfloat162_rn(v0, v1);
        g_WcatP[idx] = *(unsigned*)&p;
    } else if (bid < 288){
        int r = bid-192; int j0=(r%4)*32, i0=(r/4)*32;
        int tx=tid&31, ty=tid>>5;
        #pragma unroll
        for (int rr=ty; rr<32; rr+=8)
            if (j0+tx < 112) t[rr][tx] = Wt2k[(i0+rr)*112 + j0+tx];
        __syncthreads();
        #pragma unroll
        for (int rr=ty; rr<32; rr+=8)
            if (j0+rr < 112) g_Wt2kT[(j0+rr)*768 + i0+tx] = t[tx][rr];
    } else if (bid < 928){
        int r = bid-288; int j0=(r%16)*32, i0=(r/16)*32;
        int tx=tid&31, ty=tid>>5;
        #pragma unroll
        for (int rr=ty; rr<32; rr+=8) t[rr][tx] = Wg1[(i0+rr)*512 + j0+tx];
        __syncthreads();
        #pragma unroll
        for (int rr=ty; rr<32; rr+=8) g_Wg1T[(j0+rr)*1280 + i0+tx] = t[tx][rr];
    } else if (bid < 1056){
        int r = bid-928; int j0=(r%8)*32, i0=(r/8)*32;
        int tx=tid&31, ty=tid>>5;
        #pragma unroll
        for (int rr=ty; rr<32; rr+=8) t[rr][tx] = Wg2[(i0+rr)*256 + j0+tx];
        __syncthreads();
        #pragma unroll
        for (int rr=ty; rr<32; rr+=8) g_Wg2T[(j0+rr)*512 + i0+tx] = t[tx][rr];
    } else if (bid < 2400){
        const float4* yf4 = (const float4*)yfut;
        uint2* yb2 = (uint2*)g_ybf;
        const int total = NB*NH*ND/4;
        for (int i=(bid-1056)*256+tid; i<total; i+=1344*256){
            float4 yf = yf4[i];
            __nv_bfloat162 p0 = __floats2bfloat162_rn(yf.x, yf.y);
            __nv_bfloat162 p1 = __floats2bfloat162_rn(yf.z, yf.w);
            yb2[i] = make_uint2(*(unsigned*)&p0, *(unsigned*)&p1);
        }
    } else {
        int b = bid-2400;
        int d4 = tid&63, part = tid>>6;  // 4 parts x 128 rows
        const float4* p = (const float4*)enc + (size_t)b*NL*64 + d4;
        float4 s = make_float4(0.f,0.f,0.f,0.f);
        for (int l=part*128; l<part*128+128; l++){
            float4 v = p[(size_t)l*64];
            s.x+=v.x; s.y+=v.y; s.z+=v.z; s.w+=v.w;
        }
        sd[tid]=s; __syncthreads();
        if (tid<128){
            float4 o=sd[tid+128];
            sd[tid].x+=o.x; sd[tid].y+=o.y; sd[tid].z+=o.z; sd[tid].w+=o.w;
        }
        __syncthreads();
        if (tid<64){
            float4 v=sd[tid], o=sd[tid+64];
            const float inv = 1.f/(float)NL;
            v.x=(v.x+o.x)*inv; v.y=(v.y+o.y)*inv; v.z=(v.z+o.z)*inv; v.w=(v.w+o.w)*inv;
            ((float4*)g_tsg)[b*64+tid]=v;
        }
    }
}

// =============== M1: bf16 GEMM + kA1 + kC1 ===============
// blocks: [0,1008) GEMM | [1008,1456) A1 (4-batch) | [1456,3504) C1 (4-batch)
#define GA_W 2560
#define GB_BASE 5120
#define GB_W 2176
#define GSM_WORDS (5120+4352)

__device__ __forceinline__ void cpasync16(unsigned dst, const void* src){
    asm volatile("cp.async.ca.shared.global [%0], [%1], 16;\n" :: "r"(dst), "l"(src));
}
__device__ __forceinline__ float wredsum(float x){
    #pragma unroll
    for (int o=16;o>0;o>>=1) x += __shfl_down_sync(0xffffffffu,x,o);
    return x;
}

__global__ void __launch_bounds__(256) kM1(const float* __restrict__ text,
        const float* __restrict__ varp, const float* __restrict__ bt2k,
        const float* __restrict__ bg1){
    extern __shared__ unsigned smw[];
    int bid = blockIdx.x, tid = threadIdx.x;
    if (bid < 1008){
        unsigned smem_u32 = (unsigned)__cvta_generic_to_shared(smw);
        int m0 = (bid%336)*128, n0 = (bid/336)*128;
        int warp = tid>>5, lane = tid&31;
        int wm = warp & 1, wn = warp >> 1;
        int lr = lane>>2, lc = lane&3;
        float acc[4][4][4];
        #pragma unroll
        for (int a=0;a<4;a++)
          #pragma unroll
          for (int b=0;b<4;b++)
            #pragma unroll
            for (int c=0;c<4;c++) acc[a][b][c]=0.f;
        auto ldtile = [&](int tIt, int buf){
            int k0 = tIt*32, k20 = tIt*16;
            #pragma unroll
            for (int j=0;j<2;j++){
                int i = tid + j*256;
                int r = i>>2, c4 = i&3;
                unsigned dst = smem_u32 + (unsigned)((buf*GA_W + r*20 + c4*4)*4);
                cpasync16(dst, g_ybf + (size_t)(m0+r)*256 + k0 + c4*8);
            }
            #pragma unroll
            for (int j=0;j<2;j++){
                int i = tid + j*256;
                int r = i>>5, c4 = i&31;
                unsigned dst = smem_u32 + (unsigned)((GB_BASE + buf*GB_W + r*136 + c4*4)*4);
                cpasync16(dst, g_WcatP + (k20+r)*384 + n0 + c4*4);
            }
            asm volatile("cp.async.commit_group;\n");
        };
        ldtile(0, 0);
        for (int tt=0; tt<8; tt++){
            if (tt<7){ ldtile(tt+1, (tt+1)&1); asm volatile("cp.async.wait_group 1;\n"); }
            else     { asm volatile("cp.async.wait_group 0;\n"); }
            __syncthreads();
            const unsigned* Ab = smw + (tt&1)*GA_W;
            const unsigned* Bb = smw + GB_BASE + (tt&1)*GB_W;
            #pragma unroll
            for (int ks=0;ks<2;ks++){
                unsigned af[4][4], bf[4][2];
                #pragma unroll
                for (int mt=0;mt<4;mt++){
                    int r = wm*64 + mt*16 + lr;
                    const unsigned* p  = Ab + r*20 + ks*8 + lc;
                    const unsigned* p8 = Ab + (r+8)*20 + ks*8 + lc;
                    af[mt][0]=p[0]; af[mt][1]=p8[0]; af[mt][2]=p[4]; af[mt][3]=p8[4];
                }
                #pragma unroll
                for (int nt=0;nt<4;nt++){
                    int n = wn*32 + nt*8 + lr;
                    const unsigned* p = Bb + (ks*8+lc)*136 + n;
                    bf[nt][0]=p[0]; bf[nt][1]=p[4*136];
                }
                #pragma unroll
                for (int mt=0;mt<4;mt++)
                  #pragma unroll
                  for (int nt=0;nt<4;nt++){
                    asm volatile(
                      "mma.sync.aligned.m16n8k16.row.col.f32.bf16.bf16.f32 "
                      "{%0,%1,%2,%3},{%4,%5,%6,%7},{%8,%9},{%0,%1,%2,%3};\n"
                      : "+f"(acc[mt][nt][0]),"+f"(acc[mt][nt][1]),
                        "+f"(acc[mt][nt][2]),"+f"(acc[mt][nt][3])
                      : "r"(af[mt][0]),"r"(af[mt][1]),"r"(af[mt][2]),"r"(af[mt][3]),
                        "r"(bf[nt][0]),"r"(bf[nt][1]));
                  }
            }
            __syncthreads();
        }
        #pragma unroll
        for (int mt=0;mt<4;mt++){
            int r = m0 + wm*64 + mt*16 + lr;
            #pragma unroll
            for (int nt=0;nt<4;nt++){
                int c = n0 + wn*32 + nt*8 + 2*lc;
                *(float2*)&g_T[(size_t)r*384 + c]     = make_float2(acc[mt][nt][0],acc[mt][nt][1]);
                *(float2*)&g_T[(size_t)(r+8)*384 + c] = make_float2(acc[mt][nt][2],acc[mt][nt][3]);
            }
        }
    } else if (bid < 1456){
        int w = (bid-1008)*8 + (tid>>5);   // 3584 warps = 112 j x 32 bg
        int lane = tid&31;
        int j = w%112, bg = w/112;
        int b0 = bg*4;
        const float* wc = g_Wt2kT + j*NTXT;
        const float* t0 = text + (b0+0)*NTXT;
        const float* t1 = text + (b0+1)*NTXT;
        const float* t2 = text + (b0+2)*NTXT;
        const float* t3 = text + (b0+3)*NTXT;
        float a0=0.f,a1=0.f,a2=0.f,a3=0.f;
        #pragma unroll
        for (int it=0; it<24; it++){
            int i = it*32 + lane;
            float wv = wc[i];
            a0 += t0[i]*wv; a1 += t1[i]*wv; a2 += t2[i]*wv; a3 += t3[i]*wv;
        }
        a0=wredsum(a0); a1=wredsum(a1); a2=wredsum(a2); a3=wredsum(a3);
        if (lane==0){
            float bb = bt2k[j];
            g_raw[(b0+0)*112+j]=a0+bb; g_raw[(b0+1)*112+j]=a1+bb;
            g_raw[(b0+2)*112+j]=a2+bb; g_raw[(b0+3)*112+j]=a3+bb;
        }
    } else {
        int w = (bid-1456)*8 + (tid>>5);   // 16384 warps = 512 j x 32 bg
        int lane = tid&31;
        int j = w&511, bg = w>>9;
        int b0 = bg*4;
        const float4* Wt = (const float4*)(g_Wg1T + j*1280);
        float a0=0.f,a1=0.f,a2=0.f,a3=0.f;
        #pragma unroll
        for (int it=0; it<10; it++){
            int i4 = it*32 + lane;
            float4 wv = Wt[i4];
            float4 x0,x1,x2,x3;
            if (i4 < 64){
                x0=((const float4*)g_tsg)[(b0+0)*64+i4]; x1=((const float4*)g_tsg)[(b0+1)*64+i4];
                x2=((const float4*)g_tsg)[(b0+2)*64+i4]; x3=((const float4*)g_tsg)[(b0+3)*64+i4];
            } else if (i4 < 256){
                int o=i4-64;
                x0=((const float4*)text)[(b0+0)*192+o]; x1=((const float4*)text)[(b0+1)*192+o];
                x2=((const float4*)text)[(b0+2)*192+o]; x3=((const float4*)text)[(b0+3)*192+o];
            } else {
                float4 xv=((const float4*)varp)[i4-256];
                x0=xv; x1=xv; x2=xv; x3=xv;
            }
            a0 += x0.x*wv.x + x0.y*wv.y + x0.z*wv.z + x0.w*wv.w;
            a1 += x1.x*wv.x + x1.y*wv.y + x1.z*wv.z + x1.w*wv.w;
            a2 += x2.x*wv.x + x2.y*wv.y + x2.z*wv.z + x2.w*wv.w;
            a3 += x3.x*wv.x + x3.y*wv.y + x3.z*wv.z + x3.w*wv.w;
        }
        a0=wredsum(a0); a1=wredsum(a1); a2=wredsum(a2); a3=wredsum(a3);
        if (lane==0){
            float bb = bg1[j];
            g_hid[(b0+0)*512+j]=fmaxf(a0+bb,0.f); g_hid[(b0+1)*512+j]=fmaxf(a1+bb,0.f);
            g_hid[(b0+2)*512+j]=fmaxf(a2+bb,0.f); g_hid[(b0+3)*512+j]=fmaxf(a3+bb,0.f);
        }
    }
}

// =============== M2: kA2 + kC2 ===============
// blocks: [0,8) A2 | [8,1032) C2 (4-batch)
__global__ void __launch_bounds__(256) kM2(const float* __restrict__ bg2){
    __shared__ float se[256], st[256];
    int bid = blockIdx.x, tid = threadIdx.x;
    if (bid < 8){
        int gt = bid*256 + tid;
        int b = gt>>4, k = gt&15;
        const float* raw = g_raw + b*112 + k*7;
        float mu  = sigmoidf(raw[0]);
        float sig = softplusf(raw[1])*HSCALE + 1e-3f;
        float amp = softplusf(raw[2]);
        float s3=raw[3], s4=raw[4], s5=raw[5], s6=raw[6];
        float mx=fmaxf(fmaxf(s3,s4),fmaxf(s5,s6));
        float e3=__expf(s3-mx),e4=__expf(s4-mx),e5=__expf(s5-mx),e6=__expf(s6-mx);
        float es=e3+e4+e5+e6, ies=1.f/es;
        float w0=e3*ies,w1=e4*ies,w2=e5*ies,w3=e6*ies;
        float* p = g_par + gt*8;
        p[0]=mu; p[1]=1.f/sig; p[2]=amp; p[3]=w0; p[4]=w1; p[5]=w2; p[6]=w3;
        g_mu[gt]=mu;
        float ent=0.f;
        { float c0=fmaxf(w0,1e-8f); ent+=c0*__logf(c0);
          float c1=fmaxf(w1,1e-8f); ent+=c1*__logf(c1);
          float c2=fmaxf(w2,1e-8f); ent+=c2*__logf(c2);
          float c3=fmaxf(w3,1e-8f); ent+=c3*__logf(c3); }
        float tv=0.f;
        if (k>0) tv = fabsf(mu - sigmoidf(g_raw[b*112+(k-1)*7]));
        se[tid]=ent; st[tid]=tv;
        __syncthreads();
        for (int s=128;s>0;s>>=1){
            if (tid<s){ se[tid]+=se[tid+s]; st[tid]+=st[tid+s]; }
            __syncthreads();
        }
        if (tid==0){
            atomicAdd(&g_acc[3],(double)se[0]);
            atomicAdd(&g_acc[4],(double)st[0]);
        }
    } else {
        int w = (bid-8)*8 + (tid>>5);   // 8192 warps = 256 d x 32 bg
        int lane = tid&31;
        int d = w&255, bg = w>>8;
        int b0 = bg*4;
        const float4* Wt = (const float4*)(g_Wg2T + d*512);
        float a0=0.f,a1=0.f,a2=0.f,a3=0.f;
        #pragma unroll
        for (int it=0; it<4; it++){
            int i4 = it*32 + lane;
            float4 wv = Wt[i4];
            float4 h0=((const float4*)g_hid)[(b0+0)*128+i4];
            float4 h1=((const float4*)g_hid)[(b0+1)*128+i4];
            float4 h2=((const float4*)g_hid)[(b0+2)*128+i4];
            float4 h3=((const float4*)g_hid)[(b0+3)*128+i4];
            a0 += h0.x*wv.x + h0.y*wv.y + h0.z*wv.z + h0.w*wv.w;
            a1 += h1.x*wv.x + h1.y*wv.y + h1.z*wv.z + h1.w*wv.w;
            a2 += h2.x*wv.x + h2.y*wv.y + h2.z*wv.z + h2.w*wv.w;
            a3 += h3.x*wv.x + h3.y*wv.y + h3.z*wv.z + h3.w*wv.w;
        }
        a0=wredsum(a0); a1=wredsum(a1); a2=wredsum(a2); a3=wredsum(a3);
        if (lane==0){
            float bb = bg2[d];
            g_gate[(b0+0)*256+d]=sigmoidf(a0+bb); g_gate[(b0+1)*256+d]=sigmoidf(a1+bb);
            g_gate[(b0+2)*256+d]=sigmoidf(a2+bb); g_gate[(b0+3)*256+d]=sigmoidf(a3+bb);
        }
    }
}

// =============== M3: kappa + y_tir + r, one block per batch ===============
__global__ void __launch_bounds__(256) kM3(){
    __shared__ float kapS[NK*NH];   // 21504 B
    int b = blockIdx.x, tid = threadIdx.x;
    const float invNH = 1.f/(float)NH;
    #pragma unroll
    for (int q=0; q<21; q++){
        int i = tid + q*256;
        if (i < NK*NH){
            int k = i/NH, h = i - k*NH;
            const float* p = g_par + (b*NK+k)*8;
            float t=(h+0.5f)*invNH;
            float z=(t-p[0])*p[1];
            float az=fabsf(z);
            float b0=__expf(-0.5f*z*z);
            float b1=__expf(-az);
            float b2=fmaxf(1.f-az,0.f);
            float b3=(az<=1.f)?0.5f*(1.f+__cosf(3.14159265358979f*z)):0.f;
            float v = p[2]*(p[3]*b0+p[4]*b1+p[5]*b2+p[6]*b3);
            kapS[i]=v;
            g_kap[(size_t)b*NK*NH + i]=v;
        }
    }
    __syncthreads();
    for (int h=tid; h<NH; h+=256){
        float s=0.f;
        #pragma unroll
        for (int k=0;k<NK;k++) s += kapS[k*NH+h];
        g_ytir[b*NH+h]=s;
    }
    int warp = tid>>5, lane = tid&31;
    #pragma unroll
    for (int rr=0; rr<2; rr++){
        int k = warp*2+rr;
        float s=0.f;
        for (int h=lane; h<NH; h+=32) s += kapS[k*NH+h];
        s = wredsum(s);
        if (lane==0) g_r[b*NK+k] = s + 1e-6f;
    }
}

// =============== M5: kA5 + kD + kF ===============
// blocks: [0,128) A5 | [128,2816) D (grid-stride x4) | [2816,24320) F (2 rows/block)
__global__ void __launch_bounds__(256) kM5(const float* __restrict__ Wkemb,
        const float* __restrict__ bkemb, const float* __restrict__ yres,
        const float* __restrict__ yfut, const float* __restrict__ Wtir,
        const float* __restrict__ btir, const float* __restrict__ varp,
        const float* __restrict__ bfp){
    __shared__ float kapS[NK*NH];     // 21504 B
    __shared__ float kembS[NK*NEMB];  // 8192 B
    __shared__ float invS[NK];
    int bid = blockIdx.x, tid = threadIdx.x;
    if (bid < 128){
        int b = bid;
        const float* src = g_kap + (size_t)b*NK*NH;
        for (int i=tid; i<NK*NH; i+=256) kapS[i]=src[i];
        __syncthreads();
        int e = tid&127, half = tid>>7;
        float acc[8];
        #pragma unroll
        for (int kr=0;kr<8;kr++) acc[kr]=bkemb[e];
        for (int h=0;h<NH;h++){
            float w = Wkemb[h*NEMB+e];
            #pragma unroll
            for (int kr=0;kr<8;kr++) acc[kr] += kapS[(half*8+kr)*NH+h]*w;
        }
        #pragma unroll
        for (int kr=0;kr<8;kr++) kembS[(half*8+kr)*NEMB+e]=acc[kr];
        __syncthreads();
        int warp = tid>>5, lane = tid&31;
        #pragma unroll
        for (int rr=0;rr<2;rr++){
            int kr = warp*2+rr;
            float s=0.f;
            #pragma unroll
            for (int q=0;q<4;q++){ float v=kembS[kr*NEMB+lane+32*q]; s+=v*v; }
            s = wredsum(s);
            if (lane==0) invS[kr]=1.f/(sqrtf(s)+1e-8f);
        }
        __syncthreads();
        float* dst = g_kn + (size_t)b*NK*NEMB;
        #pragma unroll
        for (int kr=0;kr<8;kr++){
            int k = half*8+kr;
            dst[k*NEMB+e]=kembS[k*NEMB+e]*invS[k];
        }
    } else if (bid < 2816){
        const float4* yr4=(const float4*)yres; const float4* yf4=(const float4*)yfut;
        const float4* g4 =(const float4*)g_gate;
        const float4* wt4=(const float4*)Wtir; const float4* bt4=(const float4*)btir;
        const float4* vp4=(const float4*)varp;
        float acc=0.f;
        const int total = NB*NH*ND/4;
        for (int i=(bid-128)*256+tid; i<total; i+=2688*256){
            int d4 = i % (ND/4);
            int bh = i / (ND/4);
            int h = bh % NH, b = bh / NH;
            float s = g_ytir[b*NH+h];
            float4 yr=yr4[i], yf=yf4[i];
            float4 wt=wt4[d4], bt=bt4[d4], vp=vp4[d4];
            float4 gg=g4[b*(ND/4)+d4];
            float t0=(s*wt.x+bt.x)*vp.x, t1=(s*wt.y+bt.y)*vp.y;
            float t2=(s*wt.z+bt.z)*vp.z, t3=(s*wt.w+bt.w)*vp.w;
            float h0=yr.x+GWV*gg.x*(t0-yr.x), h1=yr.y+GWV*gg.y*(t1-yr.y);
            float h2=yr.z+GWV*gg.z*(t2-yr.z), h3=yr.w+GWV*gg.w*(t3-yr.w);
            float d0=h0-yf.x, d1=h1-yf.y, d2=h2-yf.z, d3=h3-yf.w;
            acc += d0*d0 + d1*d1 + d2*d2 + d3*d3;
        }
        float* sred = kapS;   // reuse shared
        sred[tid]=acc; __syncthreads();
        for (int s2=128;s2>0;s2>>=1){
            if (tid<s2) sred[tid]+=sred[tid+s2];
            __syncthreads();
        }
        if (tid==0) atomicAdd(&g_acc[0],(double)sred[0]);
    } else {
        int half = tid>>7, e = tid&127;
        int m = (bid-2816)*2 + half;
        int b=m/NH, h=m%NH;
        int m1=b*NH + (h>0?h-1:0);
        int m2=b*NH + (h>1?h-2:0);
        float v = g_T[(size_t)m*384+e] - g_T[(size_t)m1*384+128+e] + g_T[(size_t)m2*384+256+e] + bfp[e];
        g_fpos[(size_t)m*NEMB+e]=v;
        float sq=wredsum(v*v);
        float* wred = kapS;
        if ((tid&31)==0) wred[tid>>5]=sq;
        __syncthreads();
        if ((tid&127)==0){
            float s=wred[half*4]+wred[half*4+1]+wred[half*4+2]+wred[half*4+3];
            g_invn[m]=1.f/(sqrtf(s)+1e-8f);
        }
    }
}

// =============== kG: per-batch Sinkhorn OT + contrastive ===============
__global__ void __launch_bounds__(512) kG(const int* __restrict__ perm){
    int b=blockIdx.x, tid=threadIdx.x;
    extern __shared__ float sm[];
    float* kn   = sm;              // 2048
    float* Csh  = kn+2048;         // 5376
    float* Km   = Csh+5376;        // 5376
    float* ft   = Km+5376;         // 4128
    float* aggp = ft+4128;         // 2048
    float* aggn = aggp+2048;       // 2048
    float* u    = aggn+2048;       // 16
    float* v    = u+16;            // 336
    float* rr   = v+336;           // 16
    float* mus  = rr+16;           // 16
    float* scr  = mus+16;          // 64
    int* permi  = (int*)(scr+64);  // 128

    for (int i=tid;i<NK*NEMB;i+=512) kn[i]=g_kn[b*NK*NEMB+i];
    if (tid<NK){ rr[tid]=g_r[b*NK+tid]; mus[tid]=g_mu[b*NK+tid]; }
    if (tid<NEMB) permi[tid]=perm[tid];
    if (tid<NH) v[tid]=1.f;
    __syncthreads();
    if (tid==0){
        float t=0.f;
        #pragma unroll
        for (int kk=0;kk<NK;kk++) t+=rr[kk];
        scr[63]=1.f/t;
    }
    __syncthreads();
    if (tid<NK) rr[tid]*=scr[63];
    __syncthreads();

    int k    = tid>>5, lane = tid&31;
    int kq   = tid>>7, e    = tid&127;
    int ck   = tid>>5, chh  = tid&31;

    for (int h0=0;h0<NH;h0+=32){
        int hv=min(32,NH-h0);
        for (int i=tid;i<32*128;i+=512){
            int r2=i>>7, c=i&127;
            if (r2<hv) ft[r2*129+c]=g_fpos[((size_t)(b*NH+h0+r2))*NEMB+c];
        }
        __syncthreads();
        if (chh<hv){
            int h=h0+chh;
            float s=0.f;
            const float* knk=&kn[ck*128];
            const float* fr=&ft[chh*129];
            #pragma unroll 8
            for (int ee=0;ee<128;ee++) s+=knk[ee]*fr[ee];
            float cosv = s*g_invn[b*NH+h];
            float t=(h+0.5f)/(float)NH;
            float C = ALPHAV*(1.f-cosv) + BETAV*fmaxf(mus[ck]-t,0.f);
            Csh[ck*NH+h]=C;
            Km[ck*NH+h]=__expf(-C*(1.f/EPSV));
        }
        __syncthreads();
    }

    for (int it=0; it<NITERS; it++){
        {
            float s=0.f;
            for (int h=lane;h<NH;h+=32) s+=Km[k*NH+h]*v[h];
            s=wredsum(s);
            if (lane==0) u[k]=rr[k]/(s+1e-9f);
        }
        __syncthreads();
        if (tid<NH){
            float s=0.f;
            #pragma unroll
            for (int kk=0;kk<NK;kk++) s+=Km[kk*NH+tid]*u[kk];
            v[tid]=(1.f/(float)NH)/(s+1e-9f);
        }
        __syncthreads();
    }

    float cot=0.f;
    for (int i=tid;i<NK*NH;i+=512){
        int kk=i/NH, h=i%NH;
        float pi=u[kk]*Km[i]*v[h];
        Km[i]=pi;
        cot+=Csh[i]*pi;
    }
    cot=wredsum(cot);
    if (lane==0) scr[k]=cot;
    __syncthreads();
    if (tid==0){
        float s=0.f; for (int i=0;i<16;i++) s+=scr[i];
        atomicAdd(&g_acc[1],(double)s);
    }
    {
        float s=0.f;
        for (int h=lane;h<NH;h+=32) s+=Km[k*NH+h];
        s=wredsum(s);
        if (lane==0) scr[16+k]=1.f/(s+1e-9f);
    }
    __syncthreads();
    for (int i=tid;i<NK*NH;i+=512) Km[i]*=scr[16+i/NH];
    __syncthreads();

    float accp[4]={0,0,0,0}, accn[4]={0,0,0,0};
    for (int h0=0;h0<NH;h0+=32){
        int hv=min(32,NH-h0);
        for (int i=tid;i<32*128;i+=512){
            int r2=i>>7, c=i&127;
            if (r2<hv) ft[r2*129+c]=g_fpos[((size_t)(b*NH+h0+r2))*NEMB+c];
        }
        __syncthreads();
        for (int hh=0;hh<hv;hh++){
            float f=ft[hh*129+e];
            int h=h0+hh;
            int hn=h+SHIFT; if (hn>=NH) hn-=NH;
            #pragma unroll
            for (int j=0;j<4;j++){
                int kk=kq*4+j;
                accp[j]+=Km[kk*NH+h ]*f;
                accn[j]+=Km[kk*NH+hn]*f;
            }
        }
        __syncthreads();
    }
    #pragma unroll
    for (int j=0;j<4;j++){
        aggp[(kq*4+j)*128+e]=accp[j];
        aggn[(kq*4+j)*128+e]=accn[j];
    }
    __syncthreads();

    {
        float sp=0,sn=0,dp=0,dn=0,d2=0;
        for (int ee=lane; ee<128; ee+=32){
            float ap=aggp[k*128+ee], an=aggn[k*128+ee], kv=kn[k*128+ee];
            sp+=ap*ap; sn+=an*an; dp+=kv*ap; dn+=kv*an;
            d2+=kv*aggp[k*128+permi[ee]];
        }
        #pragma unroll
        for (int o=16;o>0;o>>=1){
            sp+=__shfl_down_sync(0xffffffffu,sp,o);
            sn+=__shfl_down_sync(0xffffffffu,sn,o);
            dp+=__shfl_down_sync(0xffffffffu,dp,o);
            dn+=__shfl_down_sync(0xffffffffu,dn,o);
            d2+=__shfl_down_sync(0xffffffffu,d2,o);
        }
        if (lane==0){
            float ip=1.f/(sqrtf(sp)+1e-8f), in_=1.f/(sqrtf(sn)+1e-8f);
            float l0=dp*ip*(1.f/TAUV), l1=dn*in_*(1.f/TAUV), l2=d2*ip*(1.f/TAUV);
            float mx=fmaxf(l0,fmaxf(l1,l2));
            float lse=mx+logf(expf(l0-mx)+expf(l1-mx)+expf(l2-mx));
            scr[32+k]=lse-l0;
        }
    }
    __syncthreads();
    if (tid==0){
        float s=0.f; for (int i=0;i<16;i++) s+=scr[32+i];
        atomicAdd(&g_acc[2],(double)s);
    }
}

// ---------------- final combine ----------------
__global__ void kZF(float* out){
    double mse = g_acc[0]/((double)NB*NH*ND);
    double cot = g_acc[1]/(double)NB;
    double del = g_acc[2]/((double)NB*NK);
    double ent = -g_acc[3]/((double)NB*NK);
    double tv  = g_acc[4]/((double)NB*(NK-1));
    out[0]=(float)(1.0*mse + 0.1*cot + 0.1*del + 0.01*ent + 0.01*tv);
}

extern "C" void kernel_launch(void* const* d_in, const int* in_sizes, int n_in,
                              void* d_out, int out_size){
    const float* y_res =(const float*)d_in[0];
    const float* text  =(const float*)d_in[1];
    const float* enc   =(const float*)d_in[2];
    const float* yfut  =(const float*)d_in[3];
    const int*   perm  =(const int*)  d_in[4];
    const float* Wt2k  =(const float*)d_in[5];
    const float* bt2k  =(const float*)d_in[6];
    const float* Wkemb =(const float*)d_in[7];
    const float* bkemb =(const float*)d_in[8];
    const float* Wtir  =(const float*)d_in[9];
    const float* btir  =(const float*)d_in[10];
    const float* varp  =(const float*)d_in[11];
    const float* Wg1   =(const float*)d_in[12];
    const float* bg1   =(const float*)d_in[13];
    const float* Wg2   =(const float*)d_in[14];
    const float* bg2   =(const float*)d_in[15];
    const float* Wfp   =(const float*)d_in[16];
    const float* bfp   =(const float*)d_in[17];
    float* out=(float*)d_out;

    size_t smG = (size_t)(2048+5376+5376+4128+2048+2048+16+336+16+16+64+128)*4;
    size_t smGEMM = (size_t)GSM_WORDS*4;
    cudaFuncSetAttribute(kG, cudaFuncAttributeMaxDynamicSharedMemorySize, (int)(96*1024));
    cudaFuncSetAttribute(kM1, cudaFuncAttributeMaxDynamicSharedMemorySize, (int)(64*1024));

    kP1<<<2528,256>>>(Wfp,Wt2k,Wg1,Wg2,yfut,enc);
    kM1<<<3504,256,smGEMM>>>(text,varp,bt2k,bg1);
    kM2<<<1032,256>>>(bg2);
    kM3<<<128,256>>>();
    kM5<<<24320,256>>>(Wkemb,bkemb,y_res,yfut,Wtir,btir,varp,bfp);
    kG<<<NB,512,smG>>>(perm);
    kZF<<<1,1>>>(out);
}